// round 13
// baseline (speedup 1.0000x reference)
#include <cuda_runtime.h>
#include <cuda_bf16.h>

#define N_NODES 4096
#define IN_F    512
#define OUT_F   1024
#define HEADS   8
#define HEAD_F  128

// Scratch (device globals — no allocation allowed)
__device__ float4         g_ci4  [HEADS * N_NODES];            // (ci, e^ci, e^{0.2ci}, -)
__device__ float4         g_cj4  [HEADS * N_NODES];            // (cj, e^cj, e^{0.2cj}, -)
__device__ unsigned short g_hT16 [OUT_F * N_NODES];            // bf16 h^T [head*128+f][n]
__device__ unsigned short g_xs16 [N_NODES * 1024];             // bf16 [x_hi(512) | x_lo(512)] per row
__device__ unsigned short g_WT16 [OUT_F * IN_F];               // bf16 W^T [head*128+f][k]
__device__ unsigned short g_WrT16[OUT_F * 1536];               // bf16 [Wr_hi | Wr_hi | Wr_lo] ^T rows
__device__ unsigned int   g_maskT[(N_NODES / 32) * N_NODES];   // word [mw][n], bit j = graph[mw*32+j][n]>0

// ---- helpers --------------------------------------------------------------
__device__ __forceinline__ unsigned smem_u32(const void* p) {
    unsigned a;
    asm("{ .reg .u64 t; cvta.to.shared.u64 t, %1; cvt.u32.u64 %0, t; }" : "=r"(a) : "l"(p));
    return a;
}
__device__ __forceinline__ void mma_bf16(float* d, const unsigned* a,
                                         unsigned b0, unsigned b1) {
    asm volatile(
        "mma.sync.aligned.m16n8k16.row.col.f32.bf16.bf16.f32 "
        "{%0,%1,%2,%3}, {%4,%5,%6,%7}, {%8,%9}, {%0,%1,%2,%3};"
        : "+f"(d[0]), "+f"(d[1]), "+f"(d[2]), "+f"(d[3])
        : "r"(a[0]), "r"(a[1]), "r"(a[2]), "r"(a[3]), "r"(b0), "r"(b1));
}
__device__ __forceinline__ void ldmatrix_x4(unsigned* d, unsigned addr) {
    asm volatile("ldmatrix.sync.aligned.m8n8.x4.shared.b16 {%0,%1,%2,%3}, [%4];"
        : "=r"(d[0]), "=r"(d[1]), "=r"(d[2]), "=r"(d[3]) : "r"(addr));
}
__device__ __forceinline__ unsigned pack_bf16x2(float lo, float hi) {
    unsigned u;
    asm("cvt.rn.bf16x2.f32 %0, %1, %2;" : "=r"(u) : "f"(hi), "f"(lo));
    return u;
}
__device__ __forceinline__ float2 unpack_bf16x2(unsigned u) {
    float2 r;
    r.x = __uint_as_float(u << 16);
    r.y = __uint_as_float(u & 0xffff0000u);
    return r;
}
__device__ __forceinline__ unsigned short bf16b(float x) {
    __nv_bfloat16 b = __float2bfloat16(x);
    return *(unsigned short*)&b;
}

// ---------------------------------------------------------------------------
// x -> split bf16: g_xs16[n] = [hi(512) | lo(512)]
// ---------------------------------------------------------------------------
__global__ __launch_bounds__(256) void xsplit_kernel(const float* __restrict__ x)
{
    int i = blockIdx.x * 256 + threadIdx.x;       // word index (2 floats)
    int n = i >> 8, kw = i & 255;
    float2 v = *(const float2*)&x[n * IN_F + kw * 2];
    unsigned hi = pack_bf16x2(v.x, v.y);
    float2 hf = unpack_bf16x2(hi);
    unsigned lo = pack_bf16x2(v.x - hf.x, v.y - hf.y);
    ((unsigned*)g_xs16)[n * 512 + kw]       = hi;
    ((unsigned*)g_xs16)[n * 512 + 256 + kw] = lo;
}

// ---------------------------------------------------------------------------
// W[h][k][f] -> g_WT16[(h*128+f)][k] bf16 (32x32 tile transpose)
// ---------------------------------------------------------------------------
__global__ __launch_bounds__(256) void wT_kernel(const float* __restrict__ W)
{
    __shared__ float s[32][33];
    const int h = blockIdx.z, k0 = blockIdx.x * 32, f0 = blockIdx.y * 32;
    const int t = threadIdx.x;
#pragma unroll
    for (int i = 0; i < 4; i++) {
        int idx = i * 256 + t, kk = idx >> 5, ff = idx & 31;
        s[kk][ff] = W[h * (IN_F * HEAD_F) + (k0 + kk) * HEAD_F + f0 + ff];
    }
    __syncthreads();
#pragma unroll
    for (int i = 0; i < 4; i++) {
        int idx = i * 256 + t, ff = idx >> 5, kk = idx & 31;
        g_WT16[(h * HEAD_F + f0 + ff) * IN_F + k0 + kk] = bf16b(s[kk][ff]);
    }
}

// ---------------------------------------------------------------------------
// W_r[k][c] -> g_WrT16[c][ [hi(512) | hi(512) | lo(512)] ]  (split transpose)
// ---------------------------------------------------------------------------
__global__ __launch_bounds__(256) void wrT_kernel(const float* __restrict__ W_r)
{
    __shared__ float s[32][33];
    const int k0 = blockIdx.x * 32, c0 = blockIdx.y * 32;
    const int t = threadIdx.x;
#pragma unroll
    for (int i = 0; i < 4; i++) {
        int idx = i * 256 + t, kk = idx >> 5, ff = idx & 31;
        s[kk][ff] = W_r[(k0 + kk) * OUT_F + c0 + ff];
    }
    __syncthreads();
#pragma unroll
    for (int i = 0; i < 4; i++) {
        int idx = i * 256 + t, ff = idx >> 5, kk = idx & 31;
        float v = s[kk][ff];
        __nv_bfloat16 hi = __float2bfloat16(v);
        __nv_bfloat16 lo = __float2bfloat16(v - __bfloat162float(hi));
        int row = (c0 + ff) * 1536;
        g_WrT16[row + (k0 + kk)]        = *(unsigned short*)&hi;
        g_WrT16[row + 512 + (k0 + kk)]  = *(unsigned short*)&hi;
        g_WrT16[row + 1024 + (k0 + kk)] = *(unsigned short*)&lo;
    }
}

// ---------------------------------------------------------------------------
// Transposed bitmask (int4 loads): g_maskT[mw*N+n] bit j = graph[mw*32+j][n]>0
// ---------------------------------------------------------------------------
__global__ __launch_bounds__(256) void maskt_kernel(const int* __restrict__ graph)
{
    const int mw = blockIdx.x;
    const int n4 = (blockIdx.y * 256 + threadIdx.x) * 4;
    const int4* gp = (const int4*)&graph[(mw * 32) * N_NODES + n4];
    unsigned w0 = 0, w1 = 0, w2 = 0, w3 = 0;
#pragma unroll
    for (int j = 0; j < 32; j++) {
        int4 gg = __ldg(&gp[j * (N_NODES / 4)]);
        w0 |= (unsigned)(gg.x > 0) << j;
        w1 |= (unsigned)(gg.y > 0) << j;
        w2 |= (unsigned)(gg.z > 0) << j;
        w3 |= (unsigned)(gg.w > 0) << j;
    }
    *(uint4*)&g_maskT[mw * N_NODES + n4] = make_uint4(w0, w1, w2, w3);
}

// ---------------------------------------------------------------------------
// bf16 GEMM h = x_hi @ W (tensor pipe, double-buffered) with FUSED epilogue:
//   - coe: ci/cj dots from fp32 accumulator fragments (+exp tables)
//   - hT:  bf16 transposed write via in-SMEM staging (FULL 128x128 tile)
// CTA = 128 rows x 1 head.  (g_h fp32 array eliminated entirely.)
// ---------------------------------------------------------------------------
__global__ __launch_bounds__(256, 2) void gemm_bf16_kernel(
    const float* __restrict__ wi, const float* __restrict__ wj)
{
    constexpr int PST = 20;
    __shared__ unsigned GS[4 * 2560];         // [A0|A1|B0|B1], 40960 B
    __shared__ float partI[2][128], partJ[2][128];

    const int t = threadIdx.x;
    const int w = t >> 5, lane = t & 31;
    const int g = lane >> 2, tig = lane & 3;
    const int warp_m = (w & 3) * 32;
    const int warp_f = (w >> 2) * 64;
    const int n0 = blockIdx.x * 128, head = blockIdx.y;

    const unsigned Ab = smem_u32(GS);
    const unsigned Bb = Ab + 20480u;
    unsigned aaddr[2][2], baddr[2][2][2];
    {
        int arow = warp_m + (lane & 15);
        int ak   = (lane >> 4) << 2;
#pragma unroll
        for (int mt = 0; mt < 2; mt++)
#pragma unroll
            for (int ks = 0; ks < 2; ks++)
                aaddr[mt][ks] = Ab + 4u * ((arow + mt * 16) * PST + ks * 8 + ak);
        int brow = warp_f + (lane >> 3) * 8 + (lane & 7);
#pragma unroll
        for (int ks = 0; ks < 2; ks++)
#pragma unroll
            for (int hf = 0; hf < 2; hf++)
#pragma unroll
                for (int ng = 0; ng < 2; ng++)
                    baddr[ks][hf][ng] = Bb + 4u * ((brow + ng * 32) * PST + ks * 8 + hf * 4);
    }

    float acc[2][8][4];
#pragma unroll
    for (int mt = 0; mt < 2; mt++)
#pragma unroll
        for (int nt = 0; nt < 8; nt++)
#pragma unroll
            for (int q = 0; q < 4; q++) acc[mt][nt][q] = 0.f;

    const uint4* xg = (const uint4*)g_xs16;   // row stride 128 u4; hi at [0,64)
    const uint4* wg = (const uint4*)g_WT16;   // row stride 64 u4
    const int sr = t >> 2, sq = t & 3;
    constexpr int S = 16;

    uint4 a0, a1, b0, b1;
    auto ldgS = [&](int s) {
        int kq = s * 4;
        a0 = __ldg(&xg[(n0 + sr) * 128 + kq + sq]);
        a1 = __ldg(&xg[(n0 + sr + 64) * 128 + kq + sq]);
        b0 = __ldg(&wg[(head * 128 + sr) * 64 + kq + sq]);
        b1 = __ldg(&wg[(head * 128 + sr + 64) * 64 + kq + sq]);
    };
    auto stsS = [&](int buf) {
        *(uint4*)&GS[buf * 2560 + sr * PST + sq * 4]        = a0;
        *(uint4*)&GS[buf * 2560 + (sr + 64) * PST + sq * 4] = a1;
        *(uint4*)&GS[5120 + buf * 2560 + sr * PST + sq * 4]        = b0;
        *(uint4*)&GS[5120 + buf * 2560 + (sr + 64) * PST + sq * 4] = b1;
    };

    ldgS(0); stsS(0);
    ldgS(1);
    __syncthreads();

    for (int s = 0; s < S; s++) {
        const unsigned mo = (s & 1) ? 10240u : 0u;
#pragma unroll
        for (int ks = 0; ks < 2; ks++) {
            unsigned af0[4], af1[4];
            ldmatrix_x4(af0, aaddr[0][ks] + mo);
            ldmatrix_x4(af1, aaddr[1][ks] + mo);
            unsigned b0a[4], b0b[4], b1a[4], b1b[4];
            ldmatrix_x4(b0a, baddr[ks][0][0] + mo);
            ldmatrix_x4(b0b, baddr[ks][0][1] + mo);
            ldmatrix_x4(b1a, baddr[ks][1][0] + mo);
            ldmatrix_x4(b1b, baddr[ks][1][1] + mo);
#pragma unroll
            for (int nt = 0; nt < 8; nt++) {
                unsigned bb0 = (nt < 4) ? b0a[nt] : b0b[nt - 4];
                unsigned bb1 = (nt < 4) ? b1a[nt] : b1b[nt - 4];
                mma_bf16(acc[0][nt], af0, bb0, bb1);
                mma_bf16(acc[1][nt], af1, bb0, bb1);
            }
        }
        if (s + 1 < S) {
            stsS((s + 1) & 1);
            if (s + 2 < S) ldgS(s + 2);
        }
        __syncthreads();
    }

    // ---- fused coe: partial dots from fp32 fragments -----------------------
    float2 wiv[8], wjv[8];
#pragma unroll
    for (int nt = 0; nt < 8; nt++) {
        int c = warp_f + nt * 8 + 2 * tig;
        wiv[nt] = __ldg((const float2*)&wi[head * HEAD_F + c]);
        wjv[nt] = __ldg((const float2*)&wj[head * HEAD_F + c]);
    }
    float pi[2][2] = {{0.f, 0.f}, {0.f, 0.f}};
    float pj[2][2] = {{0.f, 0.f}, {0.f, 0.f}};
#pragma unroll
    for (int mt = 0; mt < 2; mt++)
#pragma unroll
        for (int nt = 0; nt < 8; nt++) {
            pi[mt][0] += acc[mt][nt][0] * wiv[nt].x + acc[mt][nt][1] * wiv[nt].y;
            pi[mt][1] += acc[mt][nt][2] * wiv[nt].x + acc[mt][nt][3] * wiv[nt].y;
            pj[mt][0] += acc[mt][nt][0] * wjv[nt].x + acc[mt][nt][1] * wjv[nt].y;
            pj[mt][1] += acc[mt][nt][2] * wjv[nt].x + acc[mt][nt][3] * wjv[nt].y;
        }
#pragma unroll
    for (int o = 1; o < 4; o <<= 1)
#pragma unroll
        for (int mt = 0; mt < 2; mt++)
#pragma unroll
            for (int h2 = 0; h2 < 2; h2++) {
                pi[mt][h2] += __shfl_xor_sync(0xffffffffu, pi[mt][h2], o);
                pj[mt][h2] += __shfl_xor_sync(0xffffffffu, pj[mt][h2], o);
            }
    if (tig == 0) {
        int wn = w >> 2;
#pragma unroll
        for (int mt = 0; mt < 2; mt++) {
            int rr = warp_m + mt * 16 + g;
            partI[wn][rr]     = pi[mt][0];
            partI[wn][rr + 8] = pi[mt][1];
            partJ[wn][rr]     = pj[mt][0];
            partJ[wn][rr + 8] = pj[mt][1];
        }
    }

    // ---- fused hT: bf16 transpose via SMEM staging (reuse GS) --------------
    unsigned short* hs = (unsigned short*)GS;   // [128 f][stride 136 u16]
#pragma unroll
    for (int mt = 0; mt < 2; mt++)
#pragma unroll
        for (int nt = 0; nt < 8; nt++) {
            int c = warp_f + nt * 8 + 2 * tig;
            int rl0 = warp_m + mt * 16 + g, rl1 = rl0 + 8;
            hs[c * 136 + rl0]       = bf16b(acc[mt][nt][0]);
            hs[(c + 1) * 136 + rl0] = bf16b(acc[mt][nt][1]);
            hs[c * 136 + rl1]       = bf16b(acc[mt][nt][2]);
            hs[(c + 1) * 136 + rl1] = bf16b(acc[mt][nt][3]);
        }
    __syncthreads();

    // FULL tile write-out: 128 f x 16 uint4 (128 n) = 2048 uint4, 8 iters
#pragma unroll
    for (int i = 0; i < 8; i++) {
        int id = i * 256 + t;
        int f = id >> 4, nq = id & 15;
        uint4 v = *(const uint4*)&hs[f * 136 + nq * 8];
        *(uint4*)&g_hT16[(head * 128 + f) * N_NODES + n0 + nq * 8] = v;
    }
    if (t < 128) {
        float ci = partI[0][t] + partI[1][t];
        float cj = partJ[0][t] + partJ[1][t];
        g_ci4[head * N_NODES + n0 + t] = make_float4(ci, __expf(ci), __expf(0.2f * ci), 0.f);
        g_cj4[head * N_NODES + n0 + t] = make_float4(cj, __expf(cj), __expf(0.2f * cj), 0.f);
    }
}

// ---------------------------------------------------------------------------
// Residual GEMM (tensor pipe, 3-term bf16 split, K=1536):
//   out = [x_hi|x_lo|x_hi] @ [Wr_hi|Wr_hi|Wr_lo]^T + bias   (pure write)
// ---------------------------------------------------------------------------
__global__ __launch_bounds__(256, 2) void res_kernel(
    const float* __restrict__ bias, float* __restrict__ out)
{
    constexpr int PST = 20;
    constexpr unsigned BUFB = 128 * PST * 4u;
    __shared__ unsigned A2[2][128 * PST];
    __shared__ unsigned B2[2][128 * PST];

    const int t = threadIdx.x;
    const int w = t >> 5, lane = t & 31;
    const int g = lane >> 2, tig = lane & 3;
    const int warp_m = (w & 3) * 32;
    const int warp_f = (w >> 2) * 64;
    const int n0 = blockIdx.x * 128, head = blockIdx.y;

    const unsigned Ab = smem_u32(A2[0]), Bb = smem_u32(B2[0]);
    unsigned aaddr[2][2], baddr[2][2][2];
    {
        int arow = warp_m + (lane & 15);
        int ak   = (lane >> 4) << 2;
#pragma unroll
        for (int mt = 0; mt < 2; mt++)
#pragma unroll
            for (int ks = 0; ks < 2; ks++)
                aaddr[mt][ks] = Ab + 4u * ((arow + mt * 16) * PST + ks * 8 + ak);
        int brow = warp_f + (lane >> 3) * 8 + (lane & 7);
#pragma unroll
        for (int ks = 0; ks < 2; ks++)
#pragma unroll
            for (int hf = 0; hf < 2; hf++)
#pragma unroll
                for (int ng = 0; ng < 2; ng++)
                    baddr[ks][hf][ng] = Bb + 4u * ((brow + ng * 32) * PST + ks * 8 + hf * 4);
    }

    float acc[2][8][4];
#pragma unroll
    for (int mt = 0; mt < 2; mt++)
#pragma unroll
        for (int nt = 0; nt < 8; nt++)
#pragma unroll
            for (int q = 0; q < 4; q++) acc[mt][nt][q] = 0.f;

    const uint4* xg = (const uint4*)g_xs16;     // row 128 u4: [hi|lo]
    const uint4* wg = (const uint4*)g_WrT16;    // row 192 u4
    const int sr = t >> 2, sq = t & 3;
    constexpr int S = 48;

    uint4 a0, a1, b0, b1;
    auto ldgS = [&](int s) {
        int k3 = s * 32;
        int ak = ((k3 < 1024) ? k3 : (k3 - 1024)) >> 3;
        int bk = k3 >> 3;
        a0 = __ldg(&xg[(n0 + sr) * 128 + ak + sq]);
        a1 = __ldg(&xg[(n0 + sr + 64) * 128 + ak + sq]);
        b0 = __ldg(&wg[(head * 128 + sr) * 192 + bk + sq]);
        b1 = __ldg(&wg[(head * 128 + sr + 64) * 192 + bk + sq]);
    };
    auto stsS = [&](int buf) {
        *(uint4*)&A2[buf][sr * PST + sq * 4]        = a0;
        *(uint4*)&A2[buf][(sr + 64) * PST + sq * 4] = a1;
        *(uint4*)&B2[buf][sr * PST + sq * 4]        = b0;
        *(uint4*)&B2[buf][(sr + 64) * PST + sq * 4] = b1;
    };

    ldgS(0); stsS(0);
    ldgS(1);
    __syncthreads();

    for (int s = 0; s < S; s++) {
        const unsigned mo = (s & 1) ? BUFB : 0u;
#pragma unroll
        for (int ks = 0; ks < 2; ks++) {
            unsigned af0[4], af1[4];
            ldmatrix_x4(af0, aaddr[0][ks] + mo);
            ldmatrix_x4(af1, aaddr[1][ks] + mo);
            unsigned b0a[4], b0b[4], b1a[4], b1b[4];
            ldmatrix_x4(b0a, baddr[ks][0][0] + mo);
            ldmatrix_x4(b0b, baddr[ks][0][1] + mo);
            ldmatrix_x4(b1a, baddr[ks][1][0] + mo);
            ldmatrix_x4(b1b, baddr[ks][1][1] + mo);
#pragma unroll
            for (int nt = 0; nt < 8; nt++) {
                unsigned bb0 = (nt < 4) ? b0a[nt] : b0b[nt - 4];
                unsigned bb1 = (nt < 4) ? b1a[nt] : b1b[nt - 4];
                mma_bf16(acc[0][nt], af0, bb0, bb1);
                mma_bf16(acc[1][nt], af1, bb0, bb1);
            }
        }
        if (s + 1 < S) {
            stsS((s + 1) & 1);
            if (s + 2 < S) ldgS(s + 2);
        }
        __syncthreads();
    }

#pragma unroll
    for (int mt = 0; mt < 2; mt++) {
        const int rl0 = warp_m + mt * 16 + g;
        const int rl1 = rl0 + 8;
#pragma unroll
        for (int nt = 0; nt < 8; nt++) {
            const int col = head * HEAD_F + warp_f + nt * 8 + 2 * tig;
            float2 bb = *(const float2*)&bias[col];
            *(float2*)&out[(n0 + rl0) * OUT_F + col] =
                make_float2(acc[mt][nt][0] + bb.x, acc[mt][nt][1] + bb.y);
            *(float2*)&out[(n0 + rl1) * OUT_F + col] =
                make_float2(acc[mt][nt][2] + bb.x, acc[mt][nt][3] + bb.y);
        }
    }
}

// ---------------------------------------------------------------------------
// Attention (mma.sync bf16 + ldmatrix), BN=64 rows/CTA for wave balance,
// double-buffered, 1 sync/tile. Epilogue RMW-adds onto residual in out.
// ---------------------------------------------------------------------------
__global__ __launch_bounds__(256, 2) void attn_kernel(float* __restrict__ out)
{
    constexpr int PST = 20;
    constexpr int T = N_NODES / 32;
    __shared__ unsigned P2[2][64 * PST];      // P: 64 rows
    __shared__ unsigned H2[2][128 * PST];     // Ht: 128 f rows
    __shared__ float cjx[2][32], cja[2][32], cjb[2][32];
    __shared__ float sum_s[4][64];

    const int t = threadIdx.x;
    const int w = t >> 5, lane = t & 31;
    const int g = lane >> 2, tig = lane & 3;
    const int warp_m = (w & 3) * 16;          // 4 m-tiles of 16 rows
    const int warp_n = (w >> 2) * 64;
    const int n0 = blockIdx.x * 64, head = blockIdx.y;

    const unsigned Pb = smem_u32(P2[0]), Hb = smem_u32(H2[0]);
    unsigned aaddr[2], baddr[2][2][2];
    {
        int arow = warp_m + (lane & 15);
        int ak   = (lane >> 4) << 2;
#pragma unroll
        for (int ks = 0; ks < 2; ks++)
            aaddr[ks] = Pb + 4u * (arow * PST + ks * 8 + ak);
        int brow = warp_n + (lane >> 3) * 8 + (lane & 7);
#pragma unroll
        for (int ks = 0; ks < 2; ks++)
#pragma unroll
            for (int hf = 0; hf < 2; hf++)
#pragma unroll
                for (int ng = 0; ng < 2; ng++)
                    baddr[ks][hf][ng] = Hb + 4u * ((brow + ng * 32) * PST + ks * 8 + hf * 4);
    }

    const int r = t & 63, qh = t >> 6;        // row, key-quarter (8 keys each)
    const float4 ci = g_ci4[head * N_NODES + n0 + r];
    float rsum = 0.f;

    float acc[8][4];
#pragma unroll
    for (int nt = 0; nt < 8; nt++)
#pragma unroll
        for (int q = 0; q < 4; q++) acc[nt][q] = 0.f;

    const int hTf = t >> 2, hTq = t & 3;
    const uint4* hTg = (const uint4*)g_hT16;

    auto buildP = [&](int buf, unsigned m) {
        unsigned pw[4];
#pragma unroll
        for (int j2 = 0; j2 < 4; j2++) {
            const int k = qh * 8 + j2 * 2;
            float s0 = ci.x + cjx[buf][k];
            float pa0 = s0 > 0.f ? ci.y : ci.z;
            float pb0 = s0 > 0.f ? cja[buf][k] : cjb[buf][k];
            float p0 = ((m >> k) & 1u) ? pa0 * pb0 : 0.f;
            float s1 = ci.x + cjx[buf][k + 1];
            float pa1 = s1 > 0.f ? ci.y : ci.z;
            float pb1 = s1 > 0.f ? cja[buf][k + 1] : cjb[buf][k + 1];
            float p1 = ((m >> (k + 1)) & 1u) ? pa1 * pb1 : 0.f;
            pw[j2] = pack_bf16x2(p0, p1);
            float2 pr = unpack_bf16x2(pw[j2]);
            rsum += pr.x + pr.y;
        }
        *(uint4*)&P2[buf][r * PST + qh * 4] = make_uint4(pw[0], pw[1], pw[2], pw[3]);
    };

    // ---- prologue ----------------------------------------------------------
    if (t < 32) {
        float4 c4 = __ldg(&g_cj4[head * N_NODES + t]);
        cjx[0][t] = c4.x; cja[0][t] = c4.y; cjb[0][t] = c4.z;
    }
    unsigned mreg = __ldg(&g_maskT[n0 + r]);                       // mask(0)
    uint4 hv0 = __ldg(&hTg[(head * 128 + hTf) * (N_NODES / 8) + hTq]);
    uint4 hv1 = __ldg(&hTg[(head * 128 + hTf + 64) * (N_NODES / 8) + hTq]);
    __syncthreads();
    buildP(0, mreg);
    *(uint4*)&H2[0][hTf * PST + hTq * 4]        = hv0;
    *(uint4*)&H2[0][(hTf + 64) * PST + hTq * 4] = hv1;
    if (t < 32) {
        float4 c4 = __ldg(&g_cj4[head * N_NODES + 32 + t]);
        cjx[1][t] = c4.x; cja[1][t] = c4.y; cjb[1][t] = c4.z;
    }
    mreg = __ldg(&g_maskT[1 * N_NODES + n0 + r]);                  // mask(1)
    __syncthreads();

    for (int tile = 0; tile < T; ++tile) {
        const unsigned mo_p = (tile & 1) ? (64u * PST * 4u) : 0u;
        const unsigned mo_h = (tile & 1) ? (128u * PST * 4u) : 0u;
        const int nb = (tile + 1) & 1;
        uint4 nhv0, nhv1; float4 cjn; unsigned mn = 0;
        const bool more = (tile + 1 < T);
        if (more) {
            const int m1q = ((tile + 1) * 32) >> 3;
            nhv0 = __ldg(&hTg[(head * 128 + hTf) * (N_NODES / 8) + m1q + hTq]);
            nhv1 = __ldg(&hTg[(head * 128 + hTf + 64) * (N_NODES / 8) + m1q + hTq]);
            if (t < 32 && tile + 2 < T)
                cjn = __ldg(&g_cj4[head * N_NODES + (tile + 2) * 32 + t]);
            if (tile + 2 < T)
                mn = __ldg(&g_maskT[(tile + 2) * N_NODES + n0 + r]);
            buildP(nb, mreg);
        }

        // ---- mma(tile) ----------------------------------------------------
#pragma unroll
        for (int ks = 0; ks < 2; ks++) {
            unsigned af[4];
            ldmatrix_x4(af, aaddr[ks] + mo_p);
            unsigned b0a[4], b0b[4], b1a[4], b1b[4];
            ldmatrix_x4(b0a, baddr[ks][0][0] + mo_h);
            ldmatrix_x4(b0b, baddr[ks][0][1] + mo_h);
            ldmatrix_x4(b1a, baddr[ks][1][0] + mo_h);
            ldmatrix_x4(b1b, baddr[ks][1][1] + mo_h);
#pragma unroll
            for (int nt = 0; nt < 8; nt++) {
                unsigned b0 = (nt < 4) ? b0a[nt] : b0b[nt - 4];
                unsigned b1 = (nt < 4) ? b1a[nt] : b1b[nt - 4];
                mma_bf16(acc[nt], af, b0, b1);
            }
        }

        if (more) {
            *(uint4*)&H2[nb][hTf * PST + hTq * 4]        = nhv0;
            *(uint4*)&H2[nb][(hTf + 64) * PST + hTq * 4] = nhv1;
            if (t < 32 && tile + 2 < T) {
                cjx[tile & 1][t] = cjn.x;
                cja[tile & 1][t] = cjn.y;
                cjb[tile & 1][t] = cjn.z;
            }
            mreg = mn;
        }
        __syncthreads();
    }

    sum_s[qh][r] = rsum;
    __syncthreads();

    // ---- epilogue: out += att * inv (out holds residual + bias) ------------
    {
        const int rl0 = warp_m + g;
        const int rl1 = rl0 + 8;
        const float inv0 = 1.f / (sum_s[0][rl0] + sum_s[1][rl0] + sum_s[2][rl0] + sum_s[3][rl0]);
        const float inv1 = 1.f / (sum_s[0][rl1] + sum_s[1][rl1] + sum_s[2][rl1] + sum_s[3][rl1]);
#pragma unroll
        for (int nt = 0; nt < 8; nt++) {
            const int col = head * HEAD_F + warp_n + nt * 8 + 2 * tig;
            float2 v0 = *(float2*)&out[(n0 + rl0) * OUT_F + col];
            v0.x += acc[nt][0] * inv0;
            v0.y += acc[nt][1] * inv0;
            *(float2*)&out[(n0 + rl0) * OUT_F + col] = v0;
            float2 v1 = *(float2*)&out[(n0 + rl1) * OUT_F + col];
            v1.x += acc[nt][2] * inv1;
            v1.y += acc[nt][3] * inv1;
            *(float2*)&out[(n0 + rl1) * OUT_F + col] = v1;
        }
    }
}

// ---------------------------------------------------------------------------
extern "C" void kernel_launch(void* const* d_in, const int* in_sizes, int n_in,
                              void* d_out, int out_size)
{
    const float* x     = (const float*)d_in[0];
    const int*   graph = (const int*)  d_in[1];
    const float* W     = (const float*)d_in[2];
    const float* w_i   = (const float*)d_in[3];
    const float* w_j   = (const float*)d_in[4];
    const float* W_r   = (const float*)d_in[5];
    const float* bias  = (const float*)d_in[6];
    float* out = (float*)d_out;

    xsplit_kernel<<<(N_NODES * IN_F / 2) / 256, 256>>>(x);
    wT_kernel<<<dim3(IN_F / 32, HEAD_F / 32, HEADS), 256>>>(W);
    wrT_kernel<<<dim3(IN_F / 32, OUT_F / 32), 256>>>(W_r);
    maskt_kernel<<<dim3(N_NODES / 32, 4), 256>>>(graph);
    gemm_bf16_kernel<<<dim3(N_NODES / 128, HEADS), 256>>>(w_i, w_j);
    res_kernel<<<dim3(N_NODES / 128, HEADS), 256>>>(bias, out);
    attn_kernel<<<dim3(N_NODES / 64, HEADS), 256>>>(out);
}

// round 14
// speedup vs baseline: 1.2235x; 1.2235x over previous
#include <cuda_runtime.h>
#include <cuda_bf16.h>

#define N_NODES 4096
#define IN_F    512
#define OUT_F   1024
#define HEADS   8
#define HEAD_F  128

// Scratch (device globals — no allocation allowed)
__device__ float4         g_ci4  [HEADS * N_NODES];            // (ci, e^ci, e^{0.2ci}, -)
__device__ float4         g_cj4  [HEADS * N_NODES];            // (cj, e^cj, e^{0.2cj}, -)
__device__ unsigned short g_hT16 [OUT_F * N_NODES];            // bf16 h^T [head*128+f][n]
__device__ unsigned short g_xs16 [N_NODES * 1024];             // bf16 [x_hi(512) | x_lo(512)] per row
__device__ unsigned short g_WT16 [OUT_F * IN_F];               // bf16 W^T [head*128+f][k]
__device__ unsigned short g_WrT16[OUT_F * 1536];               // bf16 [Wr_hi | Wr_hi | Wr_lo] ^T rows
__device__ unsigned int   g_maskT[(N_NODES / 32) * N_NODES];   // word [mw][n], bit j = graph[mw*32+j][n]>0

// ---- helpers --------------------------------------------------------------
__device__ __forceinline__ unsigned smem_u32(const void* p) {
    unsigned a;
    asm("{ .reg .u64 t; cvta.to.shared.u64 t, %1; cvt.u32.u64 %0, t; }" : "=r"(a) : "l"(p));
    return a;
}
__device__ __forceinline__ void mma_bf16(float* d, const unsigned* a,
                                         unsigned b0, unsigned b1) {
    asm volatile(
        "mma.sync.aligned.m16n8k16.row.col.f32.bf16.bf16.f32 "
        "{%0,%1,%2,%3}, {%4,%5,%6,%7}, {%8,%9}, {%0,%1,%2,%3};"
        : "+f"(d[0]), "+f"(d[1]), "+f"(d[2]), "+f"(d[3])
        : "r"(a[0]), "r"(a[1]), "r"(a[2]), "r"(a[3]), "r"(b0), "r"(b1));
}
__device__ __forceinline__ void ldmatrix_x4(unsigned* d, unsigned addr) {
    asm volatile("ldmatrix.sync.aligned.m8n8.x4.shared.b16 {%0,%1,%2,%3}, [%4];"
        : "=r"(d[0]), "=r"(d[1]), "=r"(d[2]), "=r"(d[3]) : "r"(addr));
}
__device__ __forceinline__ unsigned pack_bf16x2(float lo, float hi) {
    unsigned u;
    asm("cvt.rn.bf16x2.f32 %0, %1, %2;" : "=r"(u) : "f"(hi), "f"(lo));
    return u;
}
__device__ __forceinline__ float2 unpack_bf16x2(unsigned u) {
    float2 r;
    r.x = __uint_as_float(u << 16);
    r.y = __uint_as_float(u & 0xffff0000u);
    return r;
}
__device__ __forceinline__ unsigned short bf16b(float x) {
    __nv_bfloat16 b = __float2bfloat16(x);
    return *(unsigned short*)&b;
}

// ---------------------------------------------------------------------------
// x -> split bf16: g_xs16[n] = [hi(512) | lo(512)]
// ---------------------------------------------------------------------------
__global__ __launch_bounds__(256) void xsplit_kernel(const float* __restrict__ x)
{
    int i = blockIdx.x * 256 + threadIdx.x;       // word index (2 floats)
    int n = i >> 8, kw = i & 255;
    float2 v = *(const float2*)&x[n * IN_F + kw * 2];
    unsigned hi = pack_bf16x2(v.x, v.y);
    float2 hf = unpack_bf16x2(hi);
    unsigned lo = pack_bf16x2(v.x - hf.x, v.y - hf.y);
    ((unsigned*)g_xs16)[n * 512 + kw]       = hi;
    ((unsigned*)g_xs16)[n * 512 + 256 + kw] = lo;
}

// ---------------------------------------------------------------------------
// W[h][k][f] -> g_WT16[(h*128+f)][k] bf16 (32x32 tile transpose)
// ---------------------------------------------------------------------------
__global__ __launch_bounds__(256) void wT_kernel(const float* __restrict__ W)
{
    __shared__ float s[32][33];
    const int h = blockIdx.z, k0 = blockIdx.x * 32, f0 = blockIdx.y * 32;
    const int t = threadIdx.x;
#pragma unroll
    for (int i = 0; i < 4; i++) {
        int idx = i * 256 + t, kk = idx >> 5, ff = idx & 31;
        s[kk][ff] = W[h * (IN_F * HEAD_F) + (k0 + kk) * HEAD_F + f0 + ff];
    }
    __syncthreads();
#pragma unroll
    for (int i = 0; i < 4; i++) {
        int idx = i * 256 + t, ff = idx >> 5, kk = idx & 31;
        g_WT16[(h * HEAD_F + f0 + ff) * IN_F + k0 + kk] = bf16b(s[kk][ff]);
    }
}

// ---------------------------------------------------------------------------
// W_r[k][c] -> g_WrT16[c][ [hi(512) | hi(512) | lo(512)] ]  (split transpose)
// ---------------------------------------------------------------------------
__global__ __launch_bounds__(256) void wrT_kernel(const float* __restrict__ W_r)
{
    __shared__ float s[32][33];
    const int k0 = blockIdx.x * 32, c0 = blockIdx.y * 32;
    const int t = threadIdx.x;
#pragma unroll
    for (int i = 0; i < 4; i++) {
        int idx = i * 256 + t, kk = idx >> 5, ff = idx & 31;
        s[kk][ff] = W_r[(k0 + kk) * OUT_F + c0 + ff];
    }
    __syncthreads();
#pragma unroll
    for (int i = 0; i < 4; i++) {
        int idx = i * 256 + t, ff = idx >> 5, kk = idx & 31;
        float v = s[kk][ff];
        __nv_bfloat16 hi = __float2bfloat16(v);
        __nv_bfloat16 lo = __float2bfloat16(v - __bfloat162float(hi));
        int row = (c0 + ff) * 1536;
        g_WrT16[row + (k0 + kk)]        = *(unsigned short*)&hi;
        g_WrT16[row + 512 + (k0 + kk)]  = *(unsigned short*)&hi;
        g_WrT16[row + 1024 + (k0 + kk)] = *(unsigned short*)&lo;
    }
}

// ---------------------------------------------------------------------------
// Transposed bitmask (int4 loads): g_maskT[mw*N+n] bit j = graph[mw*32+j][n]>0
// ---------------------------------------------------------------------------
__global__ __launch_bounds__(256) void maskt_kernel(const int* __restrict__ graph)
{
    const int mw = blockIdx.x;
    const int n4 = (blockIdx.y * 256 + threadIdx.x) * 4;
    const int4* gp = (const int4*)&graph[(mw * 32) * N_NODES + n4];
    unsigned w0 = 0, w1 = 0, w2 = 0, w3 = 0;
#pragma unroll
    for (int j = 0; j < 32; j++) {
        int4 gg = __ldg(&gp[j * (N_NODES / 4)]);
        w0 |= (unsigned)(gg.x > 0) << j;
        w1 |= (unsigned)(gg.y > 0) << j;
        w2 |= (unsigned)(gg.z > 0) << j;
        w3 |= (unsigned)(gg.w > 0) << j;
    }
    *(uint4*)&g_maskT[mw * N_NODES + n4] = make_uint4(w0, w1, w2, w3);
}

// ---------------------------------------------------------------------------
// bf16 GEMM h = x_hi @ W (tensor pipe, double-buffered) with FUSED epilogue:
//   - coe: ci/cj dots from fp32 accumulator fragments (+exp tables)
//   - hT:  bf16 transposed write via in-SMEM staging (FULL 128x128 tile)
// CTA = 128 rows x 1 head.
// ---------------------------------------------------------------------------
__global__ __launch_bounds__(256, 2) void gemm_bf16_kernel(
    const float* __restrict__ wi, const float* __restrict__ wj)
{
    constexpr int PST = 20;
    __shared__ unsigned GS[4 * 2560];         // [A0|A1|B0|B1], 40960 B
    __shared__ float partI[2][128], partJ[2][128];

    const int t = threadIdx.x;
    const int w = t >> 5, lane = t & 31;
    const int g = lane >> 2, tig = lane & 3;
    const int warp_m = (w & 3) * 32;
    const int warp_f = (w >> 2) * 64;
    const int n0 = blockIdx.x * 128, head = blockIdx.y;

    const unsigned Ab = smem_u32(GS);
    const unsigned Bb = Ab + 20480u;
    unsigned aaddr[2][2], baddr[2][2][2];
    {
        int arow = warp_m + (lane & 15);
        int ak   = (lane >> 4) << 2;
#pragma unroll
        for (int mt = 0; mt < 2; mt++)
#pragma unroll
            for (int ks = 0; ks < 2; ks++)
                aaddr[mt][ks] = Ab + 4u * ((arow + mt * 16) * PST + ks * 8 + ak);
        int brow = warp_f + (lane >> 3) * 8 + (lane & 7);
#pragma unroll
        for (int ks = 0; ks < 2; ks++)
#pragma unroll
            for (int hf = 0; hf < 2; hf++)
#pragma unroll
                for (int ng = 0; ng < 2; ng++)
                    baddr[ks][hf][ng] = Bb + 4u * ((brow + ng * 32) * PST + ks * 8 + hf * 4);
    }

    float acc[2][8][4];
#pragma unroll
    for (int mt = 0; mt < 2; mt++)
#pragma unroll
        for (int nt = 0; nt < 8; nt++)
#pragma unroll
            for (int q = 0; q < 4; q++) acc[mt][nt][q] = 0.f;

    const uint4* xg = (const uint4*)g_xs16;   // row stride 128 u4; hi at [0,64)
    const uint4* wg = (const uint4*)g_WT16;   // row stride 64 u4
    const int sr = t >> 2, sq = t & 3;
    constexpr int S = 16;

    uint4 a0, a1, b0, b1;
    auto ldgS = [&](int s) {
        int kq = s * 4;
        a0 = __ldg(&xg[(n0 + sr) * 128 + kq + sq]);
        a1 = __ldg(&xg[(n0 + sr + 64) * 128 + kq + sq]);
        b0 = __ldg(&wg[(head * 128 + sr) * 64 + kq + sq]);
        b1 = __ldg(&wg[(head * 128 + sr + 64) * 64 + kq + sq]);
    };
    auto stsS = [&](int buf) {
        *(uint4*)&GS[buf * 2560 + sr * PST + sq * 4]        = a0;
        *(uint4*)&GS[buf * 2560 + (sr + 64) * PST + sq * 4] = a1;
        *(uint4*)&GS[5120 + buf * 2560 + sr * PST + sq * 4]        = b0;
        *(uint4*)&GS[5120 + buf * 2560 + (sr + 64) * PST + sq * 4] = b1;
    };

    ldgS(0); stsS(0);
    ldgS(1);
    __syncthreads();

    for (int s = 0; s < S; s++) {
        const unsigned mo = (s & 1) ? 10240u : 0u;
#pragma unroll
        for (int ks = 0; ks < 2; ks++) {
            unsigned af0[4], af1[4];
            ldmatrix_x4(af0, aaddr[0][ks] + mo);
            ldmatrix_x4(af1, aaddr[1][ks] + mo);
            unsigned b0a[4], b0b[4], b1a[4], b1b[4];
            ldmatrix_x4(b0a, baddr[ks][0][0] + mo);
            ldmatrix_x4(b0b, baddr[ks][0][1] + mo);
            ldmatrix_x4(b1a, baddr[ks][1][0] + mo);
            ldmatrix_x4(b1b, baddr[ks][1][1] + mo);
#pragma unroll
            for (int nt = 0; nt < 8; nt++) {
                unsigned bb0 = (nt < 4) ? b0a[nt] : b0b[nt - 4];
                unsigned bb1 = (nt < 4) ? b1a[nt] : b1b[nt - 4];
                mma_bf16(acc[0][nt], af0, bb0, bb1);
                mma_bf16(acc[1][nt], af1, bb0, bb1);
            }
        }
        if (s + 1 < S) {
            stsS((s + 1) & 1);
            if (s + 2 < S) ldgS(s + 2);
        }
        __syncthreads();
    }

    // ---- fused coe: partial dots from fp32 fragments -----------------------
    float2 wiv[8], wjv[8];
#pragma unroll
    for (int nt = 0; nt < 8; nt++) {
        int c = warp_f + nt * 8 + 2 * tig;
        wiv[nt] = __ldg((const float2*)&wi[head * HEAD_F + c]);
        wjv[nt] = __ldg((const float2*)&wj[head * HEAD_F + c]);
    }
    float pi[2][2] = {{0.f, 0.f}, {0.f, 0.f}};
    float pj[2][2] = {{0.f, 0.f}, {0.f, 0.f}};
#pragma unroll
    for (int mt = 0; mt < 2; mt++)
#pragma unroll
        for (int nt = 0; nt < 8; nt++) {
            pi[mt][0] += acc[mt][nt][0] * wiv[nt].x + acc[mt][nt][1] * wiv[nt].y;
            pi[mt][1] += acc[mt][nt][2] * wiv[nt].x + acc[mt][nt][3] * wiv[nt].y;
            pj[mt][0] += acc[mt][nt][0] * wjv[nt].x + acc[mt][nt][1] * wjv[nt].y;
            pj[mt][1] += acc[mt][nt][2] * wjv[nt].x + acc[mt][nt][3] * wjv[nt].y;
        }
#pragma unroll
    for (int o = 1; o < 4; o <<= 1)
#pragma unroll
        for (int mt = 0; mt < 2; mt++)
#pragma unroll
            for (int h2 = 0; h2 < 2; h2++) {
                pi[mt][h2] += __shfl_xor_sync(0xffffffffu, pi[mt][h2], o);
                pj[mt][h2] += __shfl_xor_sync(0xffffffffu, pj[mt][h2], o);
            }
    if (tig == 0) {
        int wn = w >> 2;
#pragma unroll
        for (int mt = 0; mt < 2; mt++) {
            int rr = warp_m + mt * 16 + g;
            partI[wn][rr]     = pi[mt][0];
            partI[wn][rr + 8] = pi[mt][1];
            partJ[wn][rr]     = pj[mt][0];
            partJ[wn][rr + 8] = pj[mt][1];
        }
    }

    // ---- fused hT: bf16 transpose via SMEM staging (reuse GS) --------------
    unsigned short* hs = (unsigned short*)GS;   // [128 f][stride 136 u16]
#pragma unroll
    for (int mt = 0; mt < 2; mt++)
#pragma unroll
        for (int nt = 0; nt < 8; nt++) {
            int c = warp_f + nt * 8 + 2 * tig;
            int rl0 = warp_m + mt * 16 + g, rl1 = rl0 + 8;
            hs[c * 136 + rl0]       = bf16b(acc[mt][nt][0]);
            hs[(c + 1) * 136 + rl0] = bf16b(acc[mt][nt][1]);
            hs[c * 136 + rl1]       = bf16b(acc[mt][nt][2]);
            hs[(c + 1) * 136 + rl1] = bf16b(acc[mt][nt][3]);
        }
    __syncthreads();

    // FULL tile write-out: 128 f x 16 uint4 (128 n) = 2048 uint4, 8 iters
#pragma unroll
    for (int i = 0; i < 8; i++) {
        int id = i * 256 + t;
        int f = id >> 4, nq = id & 15;
        uint4 v = *(const uint4*)&hs[f * 136 + nq * 8];
        *(uint4*)&g_hT16[(head * 128 + f) * N_NODES + n0 + nq * 8] = v;
    }
    if (t < 128) {
        float ci = partI[0][t] + partI[1][t];
        float cj = partJ[0][t] + partJ[1][t];
        g_ci4[head * N_NODES + n0 + t] = make_float4(ci, __expf(ci), __expf(0.2f * ci), 0.f);
        g_cj4[head * N_NODES + n0 + t] = make_float4(cj, __expf(cj), __expf(0.2f * cj), 0.f);
    }
}

// ---------------------------------------------------------------------------
// Residual GEMM (tensor pipe, 3-term bf16 split, K=1536):
//   out = [x_hi|x_lo|x_hi] @ [Wr_hi|Wr_hi|Wr_lo]^T + bias   (pure write)
// ---------------------------------------------------------------------------
__global__ __launch_bounds__(256, 2) void res_kernel(
    const float* __restrict__ bias, float* __restrict__ out)
{
    constexpr int PST = 20;
    constexpr unsigned BUFB = 128 * PST * 4u;
    __shared__ unsigned A2[2][128 * PST];
    __shared__ unsigned B2[2][128 * PST];

    const int t = threadIdx.x;
    const int w = t >> 5, lane = t & 31;
    const int g = lane >> 2, tig = lane & 3;
    const int warp_m = (w & 3) * 32;
    const int warp_f = (w >> 2) * 64;
    const int n0 = blockIdx.x * 128, head = blockIdx.y;

    const unsigned Ab = smem_u32(A2[0]), Bb = smem_u32(B2[0]);
    unsigned aaddr[2][2], baddr[2][2][2];
    {
        int arow = warp_m + (lane & 15);
        int ak   = (lane >> 4) << 2;
#pragma unroll
        for (int mt = 0; mt < 2; mt++)
#pragma unroll
            for (int ks = 0; ks < 2; ks++)
                aaddr[mt][ks] = Ab + 4u * ((arow + mt * 16) * PST + ks * 8 + ak);
        int brow = warp_f + (lane >> 3) * 8 + (lane & 7);
#pragma unroll
        for (int ks = 0; ks < 2; ks++)
#pragma unroll
            for (int hf = 0; hf < 2; hf++)
#pragma unroll
                for (int ng = 0; ng < 2; ng++)
                    baddr[ks][hf][ng] = Bb + 4u * ((brow + ng * 32) * PST + ks * 8 + hf * 4);
    }

    float acc[2][8][4];
#pragma unroll
    for (int mt = 0; mt < 2; mt++)
#pragma unroll
        for (int nt = 0; nt < 8; nt++)
#pragma unroll
            for (int q = 0; q < 4; q++) acc[mt][nt][q] = 0.f;

    const uint4* xg = (const uint4*)g_xs16;     // row 128 u4: [hi|lo]
    const uint4* wg = (const uint4*)g_WrT16;    // row 192 u4
    const int sr = t >> 2, sq = t & 3;
    constexpr int S = 48;

    uint4 a0, a1, b0, b1;
    auto ldgS = [&](int s) {
        int k3 = s * 32;
        int ak = ((k3 < 1024) ? k3 : (k3 - 1024)) >> 3;
        int bk = k3 >> 3;
        a0 = __ldg(&xg[(n0 + sr) * 128 + ak + sq]);
        a1 = __ldg(&xg[(n0 + sr + 64) * 128 + ak + sq]);
        b0 = __ldg(&wg[(head * 128 + sr) * 192 + bk + sq]);
        b1 = __ldg(&wg[(head * 128 + sr + 64) * 192 + bk + sq]);
    };
    auto stsS = [&](int buf) {
        *(uint4*)&A2[buf][sr * PST + sq * 4]        = a0;
        *(uint4*)&A2[buf][(sr + 64) * PST + sq * 4] = a1;
        *(uint4*)&B2[buf][sr * PST + sq * 4]        = b0;
        *(uint4*)&B2[buf][(sr + 64) * PST + sq * 4] = b1;
    };

    ldgS(0); stsS(0);
    ldgS(1);
    __syncthreads();

    for (int s = 0; s < S; s++) {
        const unsigned mo = (s & 1) ? BUFB : 0u;
#pragma unroll
        for (int ks = 0; ks < 2; ks++) {
            unsigned af0[4], af1[4];
            ldmatrix_x4(af0, aaddr[0][ks] + mo);
            ldmatrix_x4(af1, aaddr[1][ks] + mo);
            unsigned b0a[4], b0b[4], b1a[4], b1b[4];
            ldmatrix_x4(b0a, baddr[ks][0][0] + mo);
            ldmatrix_x4(b0b, baddr[ks][0][1] + mo);
            ldmatrix_x4(b1a, baddr[ks][1][0] + mo);
            ldmatrix_x4(b1b, baddr[ks][1][1] + mo);
#pragma unroll
            for (int nt = 0; nt < 8; nt++) {
                unsigned bb0 = (nt < 4) ? b0a[nt] : b0b[nt - 4];
                unsigned bb1 = (nt < 4) ? b1a[nt] : b1b[nt - 4];
                mma_bf16(acc[0][nt], af0, bb0, bb1);
                mma_bf16(acc[1][nt], af1, bb0, bb1);
            }
        }
        if (s + 1 < S) {
            stsS((s + 1) & 1);
            if (s + 2 < S) ldgS(s + 2);
        }
        __syncthreads();
    }

#pragma unroll
    for (int mt = 0; mt < 2; mt++) {
        const int rl0 = warp_m + mt * 16 + g;
        const int rl1 = rl0 + 8;
#pragma unroll
        for (int nt = 0; nt < 8; nt++) {
            const int col = head * HEAD_F + warp_f + nt * 8 + 2 * tig;
            float2 bb = *(const float2*)&bias[col];
            *(float2*)&out[(n0 + rl0) * OUT_F + col] =
                make_float2(acc[mt][nt][0] + bb.x, acc[mt][nt][1] + bb.y);
            *(float2*)&out[(n0 + rl1) * OUT_F + col] =
                make_float2(acc[mt][nt][2] + bb.x, acc[mt][nt][3] + bb.y);
        }
    }
}

// ---------------------------------------------------------------------------
// Attention (mma.sync bf16 + ldmatrix), BN=128 rows/CTA (proven R10 config),
// double-buffered, 1 sync/tile. Epilogue RMW-adds onto residual in out.
// ---------------------------------------------------------------------------
__global__ __launch_bounds__(256, 2) void attn_kernel(float* __restrict__ out)
{
    constexpr int PST = 20;
    constexpr unsigned BUFB = 128 * PST * 4u;
    constexpr int T = N_NODES / 32;
    __shared__ unsigned P2[2][128 * PST];
    __shared__ unsigned H2[2][128 * PST];
    __shared__ float cjx[2][32], cja[2][32], cjb[2][32];
    __shared__ float sum_s[2][128];

    const int t = threadIdx.x;
    const int w = t >> 5, lane = t & 31;
    const int g = lane >> 2, tig = lane & 3;
    const int warp_m = (w & 3) * 32;
    const int warp_n = (w >> 2) * 64;
    const int n0 = blockIdx.x * 128, head = blockIdx.y;

    const unsigned Pb = smem_u32(P2[0]), Hb = smem_u32(H2[0]);
    unsigned aaddr[2][2], baddr[2][2][2];
    {
        int arow = warp_m + (lane & 15);
        int ak   = (lane >> 4) << 2;
#pragma unroll
        for (int mt = 0; mt < 2; mt++)
#pragma unroll
            for (int ks = 0; ks < 2; ks++)
                aaddr[mt][ks] = Pb + 4u * ((arow + mt * 16) * PST + ks * 8 + ak);
        int brow = warp_n + (lane >> 3) * 8 + (lane & 7);
#pragma unroll
        for (int ks = 0; ks < 2; ks++)
#pragma unroll
            for (int hf = 0; hf < 2; hf++)
#pragma unroll
                for (int ng = 0; ng < 2; ng++)
                    baddr[ks][hf][ng] = Hb + 4u * ((brow + ng * 32) * PST + ks * 8 + hf * 4);
    }

    const int r = t & 127, half = t >> 7;
    const float4 ci = g_ci4[head * N_NODES + n0 + r];
    float rsum = 0.f;

    float acc[2][8][4];
#pragma unroll
    for (int mt = 0; mt < 2; mt++)
#pragma unroll
        for (int nt = 0; nt < 8; nt++)
#pragma unroll
            for (int q = 0; q < 4; q++) acc[mt][nt][q] = 0.f;

    const int hTf = t >> 2, hTq = t & 3;
    const uint4* hTg = (const uint4*)g_hT16;

    auto buildP = [&](int buf, unsigned m) {
        unsigned pw[8];
#pragma unroll
        for (int j2 = 0; j2 < 8; j2++) {
            const int k = half * 16 + j2 * 2;
            float s0 = ci.x + cjx[buf][k];
            float pa0 = s0 > 0.f ? ci.y : ci.z;
            float pb0 = s0 > 0.f ? cja[buf][k] : cjb[buf][k];
            float p0 = ((m >> k) & 1u) ? pa0 * pb0 : 0.f;
            float s1 = ci.x + cjx[buf][k + 1];
            float pa1 = s1 > 0.f ? ci.y : ci.z;
            float pb1 = s1 > 0.f ? cja[buf][k + 1] : cjb[buf][k + 1];
            float p1 = ((m >> (k + 1)) & 1u) ? pa1 * pb1 : 0.f;
            pw[j2] = pack_bf16x2(p0, p1);
            float2 pr = unpack_bf16x2(pw[j2]);
            rsum += pr.x + pr.y;
        }
        *(uint4*)&P2[buf][r * PST + half * 8]     = make_uint4(pw[0], pw[1], pw[2], pw[3]);
        *(uint4*)&P2[buf][r * PST + half * 8 + 4] = make_uint4(pw[4], pw[5], pw[6], pw[7]);
    };

    // ---- prologue ----------------------------------------------------------
    if (t < 32) {
        float4 c4 = __ldg(&g_cj4[head * N_NODES + t]);
        cjx[0][t] = c4.x; cja[0][t] = c4.y; cjb[0][t] = c4.z;
    }
    unsigned mreg = __ldg(&g_maskT[n0 + r]);                       // mask(0)
    uint4 hv0 = __ldg(&hTg[(head * 128 + hTf) * (N_NODES / 8) + hTq]);
    uint4 hv1 = __ldg(&hTg[(head * 128 + hTf + 64) * (N_NODES / 8) + hTq]);
    __syncthreads();
    buildP(0, mreg);
    *(uint4*)&H2[0][hTf * PST + hTq * 4]        = hv0;
    *(uint4*)&H2[0][(hTf + 64) * PST + hTq * 4] = hv1;
    if (t < 32) {
        float4 c4 = __ldg(&g_cj4[head * N_NODES + 32 + t]);
        cjx[1][t] = c4.x; cja[1][t] = c4.y; cjb[1][t] = c4.z;
    }
    mreg = __ldg(&g_maskT[1 * N_NODES + n0 + r]);                  // mask(1)
    __syncthreads();

    for (int tile = 0; tile < T; ++tile) {
        const unsigned mo = (tile & 1) ? BUFB : 0u;
        const int nb = (tile + 1) & 1;
        uint4 nhv0, nhv1; float4 cjn; unsigned mn = 0;
        const bool more = (tile + 1 < T);
        if (more) {
            const int m1q = ((tile + 1) * 32) >> 3;
            nhv0 = __ldg(&hTg[(head * 128 + hTf) * (N_NODES / 8) + m1q + hTq]);
            nhv1 = __ldg(&hTg[(head * 128 + hTf + 64) * (N_NODES / 8) + m1q + hTq]);
            if (t < 32 && tile + 2 < T)
                cjn = __ldg(&g_cj4[head * N_NODES + (tile + 2) * 32 + t]);
            if (tile + 2 < T)
                mn = __ldg(&g_maskT[(tile + 2) * N_NODES + n0 + r]);
            buildP(nb, mreg);
        }

        // ---- mma(tile) ----------------------------------------------------
#pragma unroll
        for (int ks = 0; ks < 2; ks++) {
            unsigned af0[4], af1[4];
            ldmatrix_x4(af0, aaddr[0][ks] + mo);
            ldmatrix_x4(af1, aaddr[1][ks] + mo);
            unsigned b0a[4], b0b[4], b1a[4], b1b[4];
            ldmatrix_x4(b0a, baddr[ks][0][0] + mo);
            ldmatrix_x4(b0b, baddr[ks][0][1] + mo);
            ldmatrix_x4(b1a, baddr[ks][1][0] + mo);
            ldmatrix_x4(b1b, baddr[ks][1][1] + mo);
#pragma unroll
            for (int nt = 0; nt < 8; nt++) {
                unsigned b0 = (nt < 4) ? b0a[nt] : b0b[nt - 4];
                unsigned b1 = (nt < 4) ? b1a[nt] : b1b[nt - 4];
                mma_bf16(acc[0][nt], af0, b0, b1);
                mma_bf16(acc[1][nt], af1, b0, b1);
            }
        }

        if (more) {
            *(uint4*)&H2[nb][hTf * PST + hTq * 4]        = nhv0;
            *(uint4*)&H2[nb][(hTf + 64) * PST + hTq * 4] = nhv1;
            if (t < 32 && tile + 2 < T) {
                cjx[tile & 1][t] = cjn.x;
                cja[tile & 1][t] = cjn.y;
                cjb[tile & 1][t] = cjn.z;
            }
            mreg = mn;
        }
        __syncthreads();
    }

    sum_s[half][r] = rsum;
    __syncthreads();

    // ---- epilogue: out += att * inv (out holds residual + bias) ------------
#pragma unroll
    for (int mt = 0; mt < 2; mt++) {
        const int rl0 = warp_m + mt * 16 + g;
        const int rl1 = rl0 + 8;
        const float inv0 = 1.f / (sum_s[0][rl0] + sum_s[1][rl0]);
        const float inv1 = 1.f / (sum_s[0][rl1] + sum_s[1][rl1]);
#pragma unroll
        for (int nt = 0; nt < 8; nt++) {
            const int col = head * HEAD_F + warp_n + nt * 8 + 2 * tig;
            float2 v0 = *(float2*)&out[(n0 + rl0) * OUT_F + col];
            v0.x += acc[mt][nt][0] * inv0;
            v0.y += acc[mt][nt][1] * inv0;
            *(float2*)&out[(n0 + rl0) * OUT_F + col] = v0;
            float2 v1 = *(float2*)&out[(n0 + rl1) * OUT_F + col];
            v1.x += acc[mt][nt][2] * inv1;
            v1.y += acc[mt][nt][3] * inv1;
            *(float2*)&out[(n0 + rl1) * OUT_F + col] = v1;
        }
    }
}

// ---------------------------------------------------------------------------
extern "C" void kernel_launch(void* const* d_in, const int* in_sizes, int n_in,
                              void* d_out, int out_size)
{
    const float* x     = (const float*)d_in[0];
    const int*   graph = (const int*)  d_in[1];
    const float* W     = (const float*)d_in[2];
    const float* w_i   = (const float*)d_in[3];
    const float* w_j   = (const float*)d_in[4];
    const float* W_r   = (const float*)d_in[5];
    const float* bias  = (const float*)d_in[6];
    float* out = (float*)d_out;

    xsplit_kernel<<<(N_NODES * IN_F / 2) / 256, 256>>>(x);
    wT_kernel<<<dim3(IN_F / 32, HEAD_F / 32, HEADS), 256>>>(W);
    wrT_kernel<<<dim3(IN_F / 32, OUT_F / 32), 256>>>(W_r);
    maskt_kernel<<<dim3(N_NODES / 32, 4), 256>>>(graph);
    gemm_bf16_kernel<<<dim3(N_NODES / 128, HEADS), 256>>>(w_i, w_j);
    res_kernel<<<dim3(N_NODES / 128, HEADS), 256>>>(bias, out);
    attn_kernel<<<dim3(N_NODES / 64 / 2, HEADS), 256>>>(out);
}

// round 16
// speedup vs baseline: 1.2523x; 1.0236x over previous
#include <cuda_runtime.h>
#include <cuda_bf16.h>

#define N_NODES 4096
#define IN_F    512
#define OUT_F   1024
#define HEADS   8
#define HEAD_F  128

// Scratch (device globals — no allocation allowed)
__device__ float4         g_ci4  [HEADS * N_NODES];            // (ci, e^ci, e^{0.2ci}, -)
__device__ float4         g_cj4  [HEADS * N_NODES];            // (cj, e^cj, e^{0.2cj}, -)
__device__ float          g_res  [N_NODES * OUT_F];            // x@W_r + bias (residual)
__device__ unsigned short g_hT16 [OUT_F * N_NODES];            // bf16 h^T [head*128+f][n]
__device__ unsigned short g_xs16 [N_NODES * 1024];             // bf16 [x_hi(512) | x_lo(512)] per row
__device__ unsigned short g_WT16 [OUT_F * IN_F];               // bf16 W^T [head*128+f][k]
__device__ unsigned short g_WrT16[OUT_F * 1536];               // bf16 [Wr_hi | Wr_hi | Wr_lo] ^T rows
__device__ unsigned int   g_maskT[(N_NODES / 32) * N_NODES];   // word [mw][n], bit j = graph[mw*32+j][n]>0

// ---- helpers --------------------------------------------------------------
__device__ __forceinline__ unsigned smem_u32(const void* p) {
    unsigned a;
    asm("{ .reg .u64 t; cvta.to.shared.u64 t, %1; cvt.u32.u64 %0, t; }" : "=r"(a) : "l"(p));
    return a;
}
__device__ __forceinline__ void mma_bf16(float* d, const unsigned* a,
                                         unsigned b0, unsigned b1) {
    asm volatile(
        "mma.sync.aligned.m16n8k16.row.col.f32.bf16.bf16.f32 "
        "{%0,%1,%2,%3}, {%4,%5,%6,%7}, {%8,%9}, {%0,%1,%2,%3};"
        : "+f"(d[0]), "+f"(d[1]), "+f"(d[2]), "+f"(d[3])
        : "r"(a[0]), "r"(a[1]), "r"(a[2]), "r"(a[3]), "r"(b0), "r"(b1));
}
__device__ __forceinline__ void ldmatrix_x4(unsigned* d, unsigned addr) {
    asm volatile("ldmatrix.sync.aligned.m8n8.x4.shared.b16 {%0,%1,%2,%3}, [%4];"
        : "=r"(d[0]), "=r"(d[1]), "=r"(d[2]), "=r"(d[3]) : "r"(addr));
}
__device__ __forceinline__ unsigned pack_bf16x2(float lo, float hi) {
    unsigned u;
    asm("cvt.rn.bf16x2.f32 %0, %1, %2;" : "=r"(u) : "f"(hi), "f"(lo));
    return u;
}
__device__ __forceinline__ float2 unpack_bf16x2(unsigned u) {
    float2 r;
    r.x = __uint_as_float(u << 16);
    r.y = __uint_as_float(u & 0xffff0000u);
    return r;
}
__device__ __forceinline__ unsigned short bf16b(float x) {
    __nv_bfloat16 b = __float2bfloat16(x);
    return *(unsigned short*)&b;
}

// ---------------------------------------------------------------------------
// x -> split bf16: g_xs16[n] = [hi(512) | lo(512)]
// ---------------------------------------------------------------------------
__global__ __launch_bounds__(256) void xsplit_kernel(const float* __restrict__ x)
{
    int i = blockIdx.x * 256 + threadIdx.x;       // word index (2 floats)
    int n = i >> 8, kw = i & 255;
    float2 v = *(const float2*)&x[n * IN_F + kw * 2];
    unsigned hi = pack_bf16x2(v.x, v.y);
    float2 hf = unpack_bf16x2(hi);
    unsigned lo = pack_bf16x2(v.x - hf.x, v.y - hf.y);
    ((unsigned*)g_xs16)[n * 512 + kw]       = hi;
    ((unsigned*)g_xs16)[n * 512 + 256 + kw] = lo;
}

// ---------------------------------------------------------------------------
// W[h][k][f] -> g_WT16[(h*128+f)][k] bf16 (32x32 tile transpose)
// ---------------------------------------------------------------------------
__global__ __launch_bounds__(256) void wT_kernel(const float* __restrict__ W)
{
    __shared__ float s[32][33];
    const int h = blockIdx.z, k0 = blockIdx.x * 32, f0 = blockIdx.y * 32;
    const int t = threadIdx.x;
#pragma unroll
    for (int i = 0; i < 4; i++) {
        int idx = i * 256 + t, kk = idx >> 5, ff = idx & 31;
        s[kk][ff] = W[h * (IN_F * HEAD_F) + (k0 + kk) * HEAD_F + f0 + ff];
    }
    __syncthreads();
#pragma unroll
    for (int i = 0; i < 4; i++) {
        int idx = i * 256 + t, ff = idx >> 5, kk = idx & 31;
        g_WT16[(h * HEAD_F + f0 + ff) * IN_F + k0 + kk] = bf16b(s[kk][ff]);
    }
}

// ---------------------------------------------------------------------------
// W_r[k][c] -> g_WrT16[c][ [hi(512) | hi(512) | lo(512)] ]  (split transpose)
// ---------------------------------------------------------------------------
__global__ __launch_bounds__(256) void wrT_kernel(const float* __restrict__ W_r)
{
    __shared__ float s[32][33];
    const int k0 = blockIdx.x * 32, c0 = blockIdx.y * 32;
    const int t = threadIdx.x;
#pragma unroll
    for (int i = 0; i < 4; i++) {
        int idx = i * 256 + t, kk = idx >> 5, ff = idx & 31;
        s[kk][ff] = W_r[(k0 + kk) * OUT_F + c0 + ff];
    }
    __syncthreads();
#pragma unroll
    for (int i = 0; i < 4; i++) {
        int idx = i * 256 + t, ff = idx >> 5, kk = idx & 31;
        float v = s[kk][ff];
        __nv_bfloat16 hi = __float2bfloat16(v);
        __nv_bfloat16 lo = __float2bfloat16(v - __bfloat162float(hi));
        int row = (c0 + ff) * 1536;
        g_WrT16[row + (k0 + kk)]        = *(unsigned short*)&hi;
        g_WrT16[row + 512 + (k0 + kk)]  = *(unsigned short*)&hi;
        g_WrT16[row + 1024 + (k0 + kk)] = *(unsigned short*)&lo;
    }
}

// ---------------------------------------------------------------------------
// Transposed bitmask (int4 loads): g_maskT[mw*N+n] bit j = graph[mw*32+j][n]>0
// ---------------------------------------------------------------------------
__global__ __launch_bounds__(256) void maskt_kernel(const int* __restrict__ graph)
{
    const int mw = blockIdx.x;
    const int n4 = (blockIdx.y * 256 + threadIdx.x) * 4;
    const int4* gp = (const int4*)&graph[(mw * 32) * N_NODES + n4];
    unsigned w0 = 0, w1 = 0, w2 = 0, w3 = 0;
#pragma unroll
    for (int j = 0; j < 32; j++) {
        int4 gg = __ldg(&gp[j * (N_NODES / 4)]);
        w0 |= (unsigned)(gg.x > 0) << j;
        w1 |= (unsigned)(gg.y > 0) << j;
        w2 |= (unsigned)(gg.z > 0) << j;
        w3 |= (unsigned)(gg.w > 0) << j;
    }
    *(uint4*)&g_maskT[mw * N_NODES + n4] = make_uint4(w0, w1, w2, w3);
}

// ---------------------------------------------------------------------------
// bf16 GEMM h = x_hi @ W (tensor pipe, double-buffered) with FUSED epilogue:
//   - coe: ci/cj dots from fp32 accumulator fragments (+exp tables)
//   - hT:  bf16 transposed write via in-SMEM staging (FULL 128x128 tile)
// CTA = 128 rows x 1 head.
// ---------------------------------------------------------------------------
__global__ __launch_bounds__(256, 2) void gemm_bf16_kernel(
    const float* __restrict__ wi, const float* __restrict__ wj)
{
    constexpr int PST = 20;
    __shared__ unsigned GS[4 * 2560];         // [A0|A1|B0|B1], 40960 B
    __shared__ float partI[2][128], partJ[2][128];

    const int t = threadIdx.x;
    const int w = t >> 5, lane = t & 31;
    const int g = lane >> 2, tig = lane & 3;
    const int warp_m = (w & 3) * 32;
    const int warp_f = (w >> 2) * 64;
    const int n0 = blockIdx.x * 128, head = blockIdx.y;

    const unsigned Ab = smem_u32(GS);
    const unsigned Bb = Ab + 20480u;
    unsigned aaddr[2][2], baddr[2][2][2];
    {
        int arow = warp_m + (lane & 15);
        int ak   = (lane >> 4) << 2;
#pragma unroll
        for (int mt = 0; mt < 2; mt++)
#pragma unroll
            for (int ks = 0; ks < 2; ks++)
                aaddr[mt][ks] = Ab + 4u * ((arow + mt * 16) * PST + ks * 8 + ak);
        int brow = warp_f + (lane >> 3) * 8 + (lane & 7);
#pragma unroll
        for (int ks = 0; ks < 2; ks++)
#pragma unroll
            for (int hf = 0; hf < 2; hf++)
#pragma unroll
                for (int ng = 0; ng < 2; ng++)
                    baddr[ks][hf][ng] = Bb + 4u * ((brow + ng * 32) * PST + ks * 8 + hf * 4);
    }

    float acc[2][8][4];
#pragma unroll
    for (int mt = 0; mt < 2; mt++)
#pragma unroll
        for (int nt = 0; nt < 8; nt++)
#pragma unroll
            for (int q = 0; q < 4; q++) acc[mt][nt][q] = 0.f;

    const uint4* xg = (const uint4*)g_xs16;   // row stride 128 u4; hi at [0,64)
    const uint4* wg = (const uint4*)g_WT16;   // row stride 64 u4
    const int sr = t >> 2, sq = t & 3;
    constexpr int S = 16;

    uint4 a0, a1, b0, b1;
    auto ldgS = [&](int s) {
        int kq = s * 4;
        a0 = __ldg(&xg[(n0 + sr) * 128 + kq + sq]);
        a1 = __ldg(&xg[(n0 + sr + 64) * 128 + kq + sq]);
        b0 = __ldg(&wg[(head * 128 + sr) * 64 + kq + sq]);
        b1 = __ldg(&wg[(head * 128 + sr + 64) * 64 + kq + sq]);
    };
    auto stsS = [&](int buf) {
        *(uint4*)&GS[buf * 2560 + sr * PST + sq * 4]        = a0;
        *(uint4*)&GS[buf * 2560 + (sr + 64) * PST + sq * 4] = a1;
        *(uint4*)&GS[5120 + buf * 2560 + sr * PST + sq * 4]        = b0;
        *(uint4*)&GS[5120 + buf * 2560 + (sr + 64) * PST + sq * 4] = b1;
    };

    ldgS(0); stsS(0);
    ldgS(1);
    __syncthreads();

    for (int s = 0; s < S; s++) {
        const unsigned mo = (s & 1) ? 10240u : 0u;
#pragma unroll
        for (int ks = 0; ks < 2; ks++) {
            unsigned af0[4], af1[4];
            ldmatrix_x4(af0, aaddr[0][ks] + mo);
            ldmatrix_x4(af1, aaddr[1][ks] + mo);
            unsigned b0a[4], b0b[4], b1a[4], b1b[4];
            ldmatrix_x4(b0a, baddr[ks][0][0] + mo);
            ldmatrix_x4(b0b, baddr[ks][0][1] + mo);
            ldmatrix_x4(b1a, baddr[ks][1][0] + mo);
            ldmatrix_x4(b1b, baddr[ks][1][1] + mo);
#pragma unroll
            for (int nt = 0; nt < 8; nt++) {
                unsigned bb0 = (nt < 4) ? b0a[nt] : b0b[nt - 4];
                unsigned bb1 = (nt < 4) ? b1a[nt] : b1b[nt - 4];
                mma_bf16(acc[0][nt], af0, bb0, bb1);
                mma_bf16(acc[1][nt], af1, bb0, bb1);
            }
        }
        if (s + 1 < S) {
            stsS((s + 1) & 1);
            if (s + 2 < S) ldgS(s + 2);
        }
        __syncthreads();
    }

    // ---- fused coe: partial dots from fp32 fragments -----------------------
    float2 wiv[8], wjv[8];
#pragma unroll
    for (int nt = 0; nt < 8; nt++) {
        int c = warp_f + nt * 8 + 2 * tig;
        wiv[nt] = __ldg((const float2*)&wi[head * HEAD_F + c]);
        wjv[nt] = __ldg((const float2*)&wj[head * HEAD_F + c]);
    }
    float pi[2][2] = {{0.f, 0.f}, {0.f, 0.f}};
    float pj[2][2] = {{0.f, 0.f}, {0.f, 0.f}};
#pragma unroll
    for (int mt = 0; mt < 2; mt++)
#pragma unroll
        for (int nt = 0; nt < 8; nt++) {
            pi[mt][0] += acc[mt][nt][0] * wiv[nt].x + acc[mt][nt][1] * wiv[nt].y;
            pi[mt][1] += acc[mt][nt][2] * wiv[nt].x + acc[mt][nt][3] * wiv[nt].y;
            pj[mt][0] += acc[mt][nt][0] * wjv[nt].x + acc[mt][nt][1] * wjv[nt].y;
            pj[mt][1] += acc[mt][nt][2] * wjv[nt].x + acc[mt][nt][3] * wjv[nt].y;
        }
#pragma unroll
    for (int o = 1; o < 4; o <<= 1)
#pragma unroll
        for (int mt = 0; mt < 2; mt++)
#pragma unroll
            for (int h2 = 0; h2 < 2; h2++) {
                pi[mt][h2] += __shfl_xor_sync(0xffffffffu, pi[mt][h2], o);
                pj[mt][h2] += __shfl_xor_sync(0xffffffffu, pj[mt][h2], o);
            }
    if (tig == 0) {
        int wn = w >> 2;
#pragma unroll
        for (int mt = 0; mt < 2; mt++) {
            int rr = warp_m + mt * 16 + g;
            partI[wn][rr]     = pi[mt][0];
            partI[wn][rr + 8] = pi[mt][1];
            partJ[wn][rr]     = pj[mt][0];
            partJ[wn][rr + 8] = pj[mt][1];
        }
    }

    // ---- fused hT: bf16 transpose via SMEM staging (reuse GS) --------------
    unsigned short* hs = (unsigned short*)GS;   // [128 f][stride 136 u16]
#pragma unroll
    for (int mt = 0; mt < 2; mt++)
#pragma unroll
        for (int nt = 0; nt < 8; nt++) {
            int c = warp_f + nt * 8 + 2 * tig;
            int rl0 = warp_m + mt * 16 + g, rl1 = rl0 + 8;
            hs[c * 136 + rl0]       = bf16b(acc[mt][nt][0]);
            hs[(c + 1) * 136 + rl0] = bf16b(acc[mt][nt][1]);
            hs[c * 136 + rl1]       = bf16b(acc[mt][nt][2]);
            hs[(c + 1) * 136 + rl1] = bf16b(acc[mt][nt][3]);
        }
    __syncthreads();

    // FULL tile write-out: 128 f x 16 uint4 (128 n) = 2048 uint4, 8 iters
#pragma unroll
    for (int i = 0; i < 8; i++) {
        int id = i * 256 + t;
        int f = id >> 4, nq = id & 15;
        uint4 v = *(const uint4*)&hs[f * 136 + nq * 8];
        *(uint4*)&g_hT16[(head * 128 + f) * N_NODES + n0 + nq * 8] = v;
    }
    if (t < 128) {
        float ci = partI[0][t] + partI[1][t];
        float cj = partJ[0][t] + partJ[1][t];
        g_ci4[head * N_NODES + n0 + t] = make_float4(ci, __expf(ci), __expf(0.2f * ci), 0.f);
        g_cj4[head * N_NODES + n0 + t] = make_float4(cj, __expf(cj), __expf(0.2f * cj), 0.f);
    }
}

// ---------------------------------------------------------------------------
// Residual GEMM (tensor pipe, 3-term bf16 split, K=1536):
//   g_res = [x_hi|x_lo|x_hi] @ [Wr_hi|Wr_hi|Wr_lo]^T + bias   (pure write)
// Runs CONCURRENTLY with gemm/attn (joined before combine_kernel).
// ---------------------------------------------------------------------------
__global__ __launch_bounds__(256, 2) void res_kernel(const float* __restrict__ bias)
{
    constexpr int PST = 20;
    constexpr unsigned BUFB = 128 * PST * 4u;
    __shared__ unsigned A2[2][128 * PST];
    __shared__ unsigned B2[2][128 * PST];

    const int t = threadIdx.x;
    const int w = t >> 5, lane = t & 31;
    const int g = lane >> 2, tig = lane & 3;
    const int warp_m = (w & 3) * 32;
    const int warp_f = (w >> 2) * 64;
    const int n0 = blockIdx.x * 128, head = blockIdx.y;

    const unsigned Ab = smem_u32(A2[0]), Bb = smem_u32(B2[0]);
    unsigned aaddr[2][2], baddr[2][2][2];
    {
        int arow = warp_m + (lane & 15);
        int ak   = (lane >> 4) << 2;
#pragma unroll
        for (int mt = 0; mt < 2; mt++)
#pragma unroll
            for (int ks = 0; ks < 2; ks++)
                aaddr[mt][ks] = Ab + 4u * ((arow + mt * 16) * PST + ks * 8 + ak);
        int brow = warp_f + (lane >> 3) * 8 + (lane & 7);
#pragma unroll
        for (int ks = 0; ks < 2; ks++)
#pragma unroll
            for (int hf = 0; hf < 2; hf++)
#pragma unroll
                for (int ng = 0; ng < 2; ng++)
                    baddr[ks][hf][ng] = Bb + 4u * ((brow + ng * 32) * PST + ks * 8 + hf * 4);
    }

    float acc[2][8][4];
#pragma unroll
    for (int mt = 0; mt < 2; mt++)
#pragma unroll
        for (int nt = 0; nt < 8; nt++)
#pragma unroll
            for (int q = 0; q < 4; q++) acc[mt][nt][q] = 0.f;

    const uint4* xg = (const uint4*)g_xs16;     // row 128 u4: [hi|lo]
    const uint4* wg = (const uint4*)g_WrT16;    // row 192 u4
    const int sr = t >> 2, sq = t & 3;
    constexpr int S = 48;

    uint4 a0, a1, b0, b1;
    auto ldgS = [&](int s) {
        int k3 = s * 32;
        int ak = ((k3 < 1024) ? k3 : (k3 - 1024)) >> 3;
        int bk = k3 >> 3;
        a0 = __ldg(&xg[(n0 + sr) * 128 + ak + sq]);
        a1 = __ldg(&xg[(n0 + sr + 64) * 128 + ak + sq]);
        b0 = __ldg(&wg[(head * 128 + sr) * 192 + bk + sq]);
        b1 = __ldg(&wg[(head * 128 + sr + 64) * 192 + bk + sq]);
    };
    auto stsS = [&](int buf) {
        *(uint4*)&A2[buf][sr * PST + sq * 4]        = a0;
        *(uint4*)&A2[buf][(sr + 64) * PST + sq * 4] = a1;
        *(uint4*)&B2[buf][sr * PST + sq * 4]        = b0;
        *(uint4*)&B2[buf][(sr + 64) * PST + sq * 4] = b1;
    };

    ldgS(0); stsS(0);
    ldgS(1);
    __syncthreads();

    for (int s = 0; s < S; s++) {
        const unsigned mo = (s & 1) ? BUFB : 0u;
#pragma unroll
        for (int ks = 0; ks < 2; ks++) {
            unsigned af0[4], af1[4];
            ldmatrix_x4(af0, aaddr[0][ks] + mo);
            ldmatrix_x4(af1, aaddr[1][ks] + mo);
            unsigned b0a[4], b0b[4], b1a[4], b1b[4];
            ldmatrix_x4(b0a, baddr[ks][0][0] + mo);
            ldmatrix_x4(b0b, baddr[ks][0][1] + mo);
            ldmatrix_x4(b1a, baddr[ks][1][0] + mo);
            ldmatrix_x4(b1b, baddr[ks][1][1] + mo);
#pragma unroll
            for (int nt = 0; nt < 8; nt++) {
                unsigned bb0 = (nt < 4) ? b0a[nt] : b0b[nt - 4];
                unsigned bb1 = (nt < 4) ? b1a[nt] : b1b[nt - 4];
                mma_bf16(acc[0][nt], af0, bb0, bb1);
                mma_bf16(acc[1][nt], af1, bb0, bb1);
            }
        }
        if (s + 1 < S) {
            stsS((s + 1) & 1);
            if (s + 2 < S) ldgS(s + 2);
        }
        __syncthreads();
    }

#pragma unroll
    for (int mt = 0; mt < 2; mt++) {
        const int rl0 = warp_m + mt * 16 + g;
        const int rl1 = rl0 + 8;
#pragma unroll
        for (int nt = 0; nt < 8; nt++) {
            const int col = head * HEAD_F + warp_f + nt * 8 + 2 * tig;
            float2 bb = *(const float2*)&bias[col];
            *(float2*)&g_res[(n0 + rl0) * OUT_F + col] =
                make_float2(acc[mt][nt][0] + bb.x, acc[mt][nt][1] + bb.y);
            *(float2*)&g_res[(n0 + rl1) * OUT_F + col] =
                make_float2(acc[mt][nt][2] + bb.x, acc[mt][nt][3] + bb.y);
        }
    }
}

// ---------------------------------------------------------------------------
// Attention (mma.sync bf16 + ldmatrix), BN=128 rows/CTA, double-buffered,
// 1 sync/tile. Epilogue: pure stores of att*inv to out.
// ---------------------------------------------------------------------------
__global__ __launch_bounds__(256, 2) void attn_kernel(float* __restrict__ out)
{
    constexpr int PST = 20;
    constexpr unsigned BUFB = 128 * PST * 4u;
    constexpr int T = N_NODES / 32;
    __shared__ unsigned P2[2][128 * PST];
    __shared__ unsigned H2[2][128 * PST];
    __shared__ float cjx[2][32], cja[2][32], cjb[2][32];
    __shared__ float sum_s[2][128];

    const int t = threadIdx.x;
    const int w = t >> 5, lane = t & 31;
    const int g = lane >> 2, tig = lane & 3;
    const int warp_m = (w & 3) * 32;
    const int warp_n = (w >> 2) * 64;
    const int n0 = blockIdx.x * 128, head = blockIdx.y;

    const unsigned Pb = smem_u32(P2[0]), Hb = smem_u32(H2[0]);
    unsigned aaddr[2][2], baddr[2][2][2];
    {
        int arow = warp_m + (lane & 15);
        int ak   = (lane >> 4) << 2;
#pragma unroll
        for (int mt = 0; mt < 2; mt++)
#pragma unroll
            for (int ks = 0; ks < 2; ks++)
                aaddr[mt][ks] = Pb + 4u * ((arow + mt * 16) * PST + ks * 8 + ak);
        int brow = warp_n + (lane >> 3) * 8 + (lane & 7);
#pragma unroll
        for (int ks = 0; ks < 2; ks++)
#pragma unroll
            for (int hf = 0; hf < 2; hf++)
#pragma unroll
                for (int ng = 0; ng < 2; ng++)
                    baddr[ks][hf][ng] = Hb + 4u * ((brow + ng * 32) * PST + ks * 8 + hf * 4);
    }

    const int r = t & 127, half = t >> 7;
    const float4 ci = g_ci4[head * N_NODES + n0 + r];
    float rsum = 0.f;

    float acc[2][8][4];
#pragma unroll
    for (int mt = 0; mt < 2; mt++)
#pragma unroll
        for (int nt = 0; nt < 8; nt++)
#pragma unroll
            for (int q = 0; q < 4; q++) acc[mt][nt][q] = 0.f;

    const int hTf = t >> 2, hTq = t & 3;
    const uint4* hTg = (const uint4*)g_hT16;

    auto buildP = [&](int buf, unsigned m) {
        unsigned pw[8];
#pragma unroll
        for (int j2 = 0; j2 < 8; j2++) {
            const int k = half * 16 + j2 * 2;
            float s0 = ci.x + cjx[buf][k];
            float pa0 = s0 > 0.f ? ci.y : ci.z;
            float pb0 = s0 > 0.f ? cja[buf][k] : cjb[buf][k];
            float p0 = ((m >> k) & 1u) ? pa0 * pb0 : 0.f;
            float s1 = ci.x + cjx[buf][k + 1];
            float pa1 = s1 > 0.f ? ci.y : ci.z;
            float pb1 = s1 > 0.f ? cja[buf][k + 1] : cjb[buf][k + 1];
            float p1 = ((m >> (k + 1)) & 1u) ? pa1 * pb1 : 0.f;
            pw[j2] = pack_bf16x2(p0, p1);
            float2 pr = unpack_bf16x2(pw[j2]);
            rsum += pr.x + pr.y;
        }
        *(uint4*)&P2[buf][r * PST + half * 8]     = make_uint4(pw[0], pw[1], pw[2], pw[3]);
        *(uint4*)&P2[buf][r * PST + half * 8 + 4] = make_uint4(pw[4], pw[5], pw[6], pw[7]);
    };

    // ---- prologue ----------------------------------------------------------
    if (t < 32) {
        float4 c4 = __ldg(&g_cj4[head * N_NODES + t]);
        cjx[0][t] = c4.x; cja[0][t] = c4.y; cjb[0][t] = c4.z;
    }
    unsigned mreg = __ldg(&g_maskT[n0 + r]);                       // mask(0)
    uint4 hv0 = __ldg(&hTg[(head * 128 + hTf) * (N_NODES / 8) + hTq]);
    uint4 hv1 = __ldg(&hTg[(head * 128 + hTf + 64) * (N_NODES / 8) + hTq]);
    __syncthreads();
    buildP(0, mreg);
    *(uint4*)&H2[0][hTf * PST + hTq * 4]        = hv0;
    *(uint4*)&H2[0][(hTf + 64) * PST + hTq * 4] = hv1;
    if (t < 32) {
        float4 c4 = __ldg(&g_cj4[head * N_NODES + 32 + t]);
        cjx[1][t] = c4.x; cja[1][t] = c4.y; cjb[1][t] = c4.z;
    }
    mreg = __ldg(&g_maskT[1 * N_NODES + n0 + r]);                  // mask(1)
    __syncthreads();

    for (int tile = 0; tile < T; ++tile) {
        const unsigned mo = (tile & 1) ? BUFB : 0u;
        const int nb = (tile + 1) & 1;
        uint4 nhv0, nhv1; float4 cjn; unsigned mn = 0;
        const bool more = (tile + 1 < T);
        if (more) {
            const int m1q = ((tile + 1) * 32) >> 3;
            nhv0 = __ldg(&hTg[(head * 128 + hTf) * (N_NODES / 8) + m1q + hTq]);
            nhv1 = __ldg(&hTg[(head * 128 + hTf + 64) * (N_NODES / 8) + m1q + hTq]);
            if (t < 32 && tile + 2 < T)
                cjn = __ldg(&g_cj4[head * N_NODES + (tile + 2) * 32 + t]);
            if (tile + 2 < T)
                mn = __ldg(&g_maskT[(tile + 2) * N_NODES + n0 + r]);
            buildP(nb, mreg);
        }

        // ---- mma(tile) ----------------------------------------------------
#pragma unroll
        for (int ks = 0; ks < 2; ks++) {
            unsigned af0[4], af1[4];
            ldmatrix_x4(af0, aaddr[0][ks] + mo);
            ldmatrix_x4(af1, aaddr[1][ks] + mo);
            unsigned b0a[4], b0b[4], b1a[4], b1b[4];
            ldmatrix_x4(b0a, baddr[ks][0][0] + mo);
            ldmatrix_x4(b0b, baddr[ks][0][1] + mo);
            ldmatrix_x4(b1a, baddr[ks][1][0] + mo);
            ldmatrix_x4(b1b, baddr[ks][1][1] + mo);
#pragma unroll
            for (int nt = 0; nt < 8; nt++) {
                unsigned b0 = (nt < 4) ? b0a[nt] : b0b[nt - 4];
                unsigned b1 = (nt < 4) ? b1a[nt] : b1b[nt - 4];
                mma_bf16(acc[0][nt], af0, b0, b1);
                mma_bf16(acc[1][nt], af1, b0, b1);
            }
        }

        if (more) {
            *(uint4*)&H2[nb][hTf * PST + hTq * 4]        = nhv0;
            *(uint4*)&H2[nb][(hTf + 64) * PST + hTq * 4] = nhv1;
            if (t < 32 && tile + 2 < T) {
                cjx[tile & 1][t] = cjn.x;
                cja[tile & 1][t] = cjn.y;
                cjb[tile & 1][t] = cjn.z;
            }
            mreg = mn;
        }
        __syncthreads();
    }

    sum_s[half][r] = rsum;
    __syncthreads();

    // ---- epilogue: out = att * inv (pure streaming stores) -----------------
#pragma unroll
    for (int mt = 0; mt < 2; mt++) {
        const int rl0 = warp_m + mt * 16 + g;
        const int rl1 = rl0 + 8;
        const float inv0 = 1.f / (sum_s[0][rl0] + sum_s[1][rl0]);
        const float inv1 = 1.f / (sum_s[0][rl1] + sum_s[1][rl1]);
#pragma unroll
        for (int nt = 0; nt < 8; nt++) {
            const int col = head * HEAD_F + warp_n + nt * 8 + 2 * tig;
            *(float2*)&out[(n0 + rl0) * OUT_F + col] =
                make_float2(acc[mt][nt][0] * inv0, acc[mt][nt][1] * inv0);
            *(float2*)&out[(n0 + rl1) * OUT_F + col] =
                make_float2(acc[mt][nt][2] * inv1, acc[mt][nt][3] * inv1);
        }
    }
}

// ---------------------------------------------------------------------------
// combine: out += g_res   (att + (res+bias); fp add commutes bit-exactly)
// ---------------------------------------------------------------------------
__global__ __launch_bounds__(256) void combine_kernel(float* __restrict__ out)
{
    int i = blockIdx.x * 256 + threadIdx.x;
    float4 o = ((float4*)out)[i];
    float4 r = ((const float4*)g_res)[i];
    o.x += r.x; o.y += r.y; o.z += r.z; o.w += r.w;
    ((float4*)out)[i] = o;
}

// ---------------------------------------------------------------------------
extern "C" void kernel_launch(void* const* d_in, const int* in_sizes, int n_in,
                              void* d_out, int out_size)
{
    const float* x     = (const float*)d_in[0];
    const int*   graph = (const int*)  d_in[1];
    const float* W     = (const float*)d_in[2];
    const float* w_i   = (const float*)d_in[3];
    const float* w_j   = (const float*)d_in[4];
    const float* W_r   = (const float*)d_in[5];
    const float* bias  = (const float*)d_in[6];
    float* out = (float*)d_out;

    // Streams/events created ONCE (first call = harness correctness run, which
    // precedes the pre-capture memory baseline). Reused on every later call, so
    // nothing is allocated during capture or replay and teardown returns to
    // baseline. The launched work is identical on every call.
    static cudaStream_t s1 = nullptr, s2 = nullptr;
    static cudaEvent_t e_fork = nullptr, e_x = nullptr, e_res = nullptr, e_m = nullptr;
    if (s1 == nullptr) {
        cudaStreamCreateWithFlags(&s1, cudaStreamNonBlocking);
        cudaStreamCreateWithFlags(&s2, cudaStreamNonBlocking);
        cudaEventCreateWithFlags(&e_fork, cudaEventDisableTiming);
        cudaEventCreateWithFlags(&e_x,    cudaEventDisableTiming);
        cudaEventCreateWithFlags(&e_res,  cudaEventDisableTiming);
        cudaEventCreateWithFlags(&e_m,    cudaEventDisableTiming);
    }

    // fork point on origin (null) stream
    cudaEventRecord(e_fork, 0);
    cudaStreamWaitEvent(s1, e_fork, 0);
    cudaStreamWaitEvent(s2, e_fork, 0);

    // s2: mask build (DRAM-bound) — overlaps tensor kernels
    maskt_kernel<<<dim3(N_NODES / 32, 4), 256, 0, s2>>>(graph);
    cudaEventRecord(e_m, s2);

    // s0 (null): x split -> (event) -> wT -> gemm
    xsplit_kernel<<<(N_NODES * IN_F / 2) / 256, 256>>>(x);
    cudaEventRecord(e_x, 0);
    wT_kernel<<<dim3(IN_F / 32, HEAD_F / 32, HEADS), 256>>>(W);
    gemm_bf16_kernel<<<dim3(N_NODES / 128, HEADS), 256>>>(w_i, w_j);

    // s1: wrT -> (wait xsplit) -> res (concurrent with gemm + attn)
    wrT_kernel<<<dim3(IN_F / 32, OUT_F / 32), 256, 0, s1>>>(W_r);
    cudaStreamWaitEvent(s1, e_x, 0);
    res_kernel<<<dim3(N_NODES / 128, HEADS), 256, 0, s1>>>(bias);
    cudaEventRecord(e_res, s1);

    // s0: attn needs gemm (program order) + maskt (event); NOT res
    cudaStreamWaitEvent(0, e_m, 0);
    attn_kernel<<<dim3(N_NODES / 128, HEADS), 256>>>(out);

    // join res, then combine
    cudaStreamWaitEvent(0, e_res, 0);
    combine_kernel<<<(N_NODES * OUT_F / 4) / 256, 256>>>(out);
}

// round 17
// speedup vs baseline: 1.2698x; 1.0140x over previous
#include <cuda_runtime.h>
#include <cuda_bf16.h>

#define N_NODES 4096
#define IN_F    512
#define OUT_F   1024
#define HEADS   8
#define HEAD_F  128

// Scratch (device globals — no allocation allowed)
__device__ float4         g_ci4  [HEADS * N_NODES];            // (ci, e^ci, e^{0.2ci}, -)
__device__ float4         g_cj4  [HEADS * N_NODES];            // (cj, e^cj, e^{0.2cj}, -)
__device__ float          g_res  [N_NODES * OUT_F];            // x@W_r + bias (residual)
__device__ float          g_att  [2 * N_NODES * OUT_F];        // unnormalized partial attn (per key-half)
__device__ float          g_rsum [2][HEADS * N_NODES];         // partial softmax denominators
__device__ unsigned short g_hT16 [OUT_F * N_NODES];            // bf16 h^T [head*128+f][n]
__device__ unsigned short g_xs16 [N_NODES * 1024];             // bf16 [x_hi(512) | x_lo(512)] per row
__device__ unsigned short g_WT16 [OUT_F * IN_F];               // bf16 W^T [head*128+f][k]
__device__ unsigned short g_WrT16[OUT_F * 1536];               // bf16 [Wr_hi | Wr_hi | Wr_lo] ^T rows
__device__ unsigned int   g_maskT[(N_NODES / 32) * N_NODES];   // word [mw][n], bit j = graph[mw*32+j][n]>0

// ---- helpers --------------------------------------------------------------
__device__ __forceinline__ unsigned smem_u32(const void* p) {
    unsigned a;
    asm("{ .reg .u64 t; cvta.to.shared.u64 t, %1; cvt.u32.u64 %0, t; }" : "=r"(a) : "l"(p));
    return a;
}
__device__ __forceinline__ void mma_bf16(float* d, const unsigned* a,
                                         unsigned b0, unsigned b1) {
    asm volatile(
        "mma.sync.aligned.m16n8k16.row.col.f32.bf16.bf16.f32 "
        "{%0,%1,%2,%3}, {%4,%5,%6,%7}, {%8,%9}, {%0,%1,%2,%3};"
        : "+f"(d[0]), "+f"(d[1]), "+f"(d[2]), "+f"(d[3])
        : "r"(a[0]), "r"(a[1]), "r"(a[2]), "r"(a[3]), "r"(b0), "r"(b1));
}
__device__ __forceinline__ void ldmatrix_x4(unsigned* d, unsigned addr) {
    asm volatile("ldmatrix.sync.aligned.m8n8.x4.shared.b16 {%0,%1,%2,%3}, [%4];"
        : "=r"(d[0]), "=r"(d[1]), "=r"(d[2]), "=r"(d[3]) : "r"(addr));
}
__device__ __forceinline__ unsigned pack_bf16x2(float lo, float hi) {
    unsigned u;
    asm("cvt.rn.bf16x2.f32 %0, %1, %2;" : "=r"(u) : "f"(hi), "f"(lo));
    return u;
}
__device__ __forceinline__ float2 unpack_bf16x2(unsigned u) {
    float2 r;
    r.x = __uint_as_float(u << 16);
    r.y = __uint_as_float(u & 0xffff0000u);
    return r;
}
__device__ __forceinline__ unsigned short bf16b(float x) {
    __nv_bfloat16 b = __float2bfloat16(x);
    return *(unsigned short*)&b;
}
#define CP_ASYNC16(dst, src) \
    asm volatile("cp.async.cg.shared.global [%0], [%1], 16;" :: "r"(dst), "l"(src) : "memory")
#define CP_COMMIT() asm volatile("cp.async.commit_group;" ::: "memory")
#define CP_WAIT0()  asm volatile("cp.async.wait_group 0;" ::: "memory")

// ---------------------------------------------------------------------------
// x -> split bf16: g_xs16[n] = [hi(512) | lo(512)]
// ---------------------------------------------------------------------------
__global__ __launch_bounds__(256) void xsplit_kernel(const float* __restrict__ x)
{
    int i = blockIdx.x * 256 + threadIdx.x;
    int n = i >> 8, kw = i & 255;
    float2 v = *(const float2*)&x[n * IN_F + kw * 2];
    unsigned hi = pack_bf16x2(v.x, v.y);
    float2 hf = unpack_bf16x2(hi);
    unsigned lo = pack_bf16x2(v.x - hf.x, v.y - hf.y);
    ((unsigned*)g_xs16)[n * 512 + kw]       = hi;
    ((unsigned*)g_xs16)[n * 512 + 256 + kw] = lo;
}

// ---------------------------------------------------------------------------
// W[h][k][f] -> g_WT16[(h*128+f)][k] bf16
// ---------------------------------------------------------------------------
__global__ __launch_bounds__(256) void wT_kernel(const float* __restrict__ W)
{
    __shared__ float s[32][33];
    const int h = blockIdx.z, k0 = blockIdx.x * 32, f0 = blockIdx.y * 32;
    const int t = threadIdx.x;
#pragma unroll
    for (int i = 0; i < 4; i++) {
        int idx = i * 256 + t, kk = idx >> 5, ff = idx & 31;
        s[kk][ff] = W[h * (IN_F * HEAD_F) + (k0 + kk) * HEAD_F + f0 + ff];
    }
    __syncthreads();
#pragma unroll
    for (int i = 0; i < 4; i++) {
        int idx = i * 256 + t, ff = idx >> 5, kk = idx & 31;
        g_WT16[(h * HEAD_F + f0 + ff) * IN_F + k0 + kk] = bf16b(s[kk][ff]);
    }
}

// ---------------------------------------------------------------------------
// W_r[k][c] -> g_WrT16[c][hi|hi|lo]
// ---------------------------------------------------------------------------
__global__ __launch_bounds__(256) void wrT_kernel(const float* __restrict__ W_r)
{
    __shared__ float s[32][33];
    const int k0 = blockIdx.x * 32, c0 = blockIdx.y * 32;
    const int t = threadIdx.x;
#pragma unroll
    for (int i = 0; i < 4; i++) {
        int idx = i * 256 + t, kk = idx >> 5, ff = idx & 31;
        s[kk][ff] = W_r[(k0 + kk) * OUT_F + c0 + ff];
    }
    __syncthreads();
#pragma unroll
    for (int i = 0; i < 4; i++) {
        int idx = i * 256 + t, ff = idx >> 5, kk = idx & 31;
        float v = s[kk][ff];
        __nv_bfloat16 hi = __float2bfloat16(v);
        __nv_bfloat16 lo = __float2bfloat16(v - __bfloat162float(hi));
        int row = (c0 + ff) * 1536;
        g_WrT16[row + (k0 + kk)]        = *(unsigned short*)&hi;
        g_WrT16[row + 512 + (k0 + kk)]  = *(unsigned short*)&hi;
        g_WrT16[row + 1024 + (k0 + kk)] = *(unsigned short*)&lo;
    }
}

// ---------------------------------------------------------------------------
// Transposed bitmask
// ---------------------------------------------------------------------------
__global__ __launch_bounds__(256) void maskt_kernel(const int* __restrict__ graph)
{
    const int mw = blockIdx.x;
    const int n4 = (blockIdx.y * 256 + threadIdx.x) * 4;
    const int4* gp = (const int4*)&graph[(mw * 32) * N_NODES + n4];
    unsigned w0 = 0, w1 = 0, w2 = 0, w3 = 0;
#pragma unroll
    for (int j = 0; j < 32; j++) {
        int4 gg = __ldg(&gp[j * (N_NODES / 4)]);
        w0 |= (unsigned)(gg.x > 0) << j;
        w1 |= (unsigned)(gg.y > 0) << j;
        w2 |= (unsigned)(gg.z > 0) << j;
        w3 |= (unsigned)(gg.w > 0) << j;
    }
    *(uint4*)&g_maskT[mw * N_NODES + n4] = make_uint4(w0, w1, w2, w3);
}

// ---------------------------------------------------------------------------
// bf16 GEMM h = x_hi @ W with FUSED coe + hT epilogue (unchanged from R16)
// ---------------------------------------------------------------------------
__global__ __launch_bounds__(256, 2) void gemm_bf16_kernel(
    const float* __restrict__ wi, const float* __restrict__ wj)
{
    constexpr int PST = 20;
    __shared__ unsigned GS[4 * 2560];
    __shared__ float partI[2][128], partJ[2][128];

    const int t = threadIdx.x;
    const int w = t >> 5, lane = t & 31;
    const int g = lane >> 2, tig = lane & 3;
    const int warp_m = (w & 3) * 32;
    const int warp_f = (w >> 2) * 64;
    const int n0 = blockIdx.x * 128, head = blockIdx.y;

    const unsigned Ab = smem_u32(GS);
    const unsigned Bb = Ab + 20480u;
    unsigned aaddr[2][2], baddr[2][2][2];
    {
        int arow = warp_m + (lane & 15);
        int ak   = (lane >> 4) << 2;
#pragma unroll
        for (int mt = 0; mt < 2; mt++)
#pragma unroll
            for (int ks = 0; ks < 2; ks++)
                aaddr[mt][ks] = Ab + 4u * ((arow + mt * 16) * PST + ks * 8 + ak);
        int brow = warp_f + (lane >> 3) * 8 + (lane & 7);
#pragma unroll
        for (int ks = 0; ks < 2; ks++)
#pragma unroll
            for (int hf = 0; hf < 2; hf++)
#pragma unroll
                for (int ng = 0; ng < 2; ng++)
                    baddr[ks][hf][ng] = Bb + 4u * ((brow + ng * 32) * PST + ks * 8 + hf * 4);
    }

    float acc[2][8][4];
#pragma unroll
    for (int mt = 0; mt < 2; mt++)
#pragma unroll
        for (int nt = 0; nt < 8; nt++)
#pragma unroll
            for (int q = 0; q < 4; q++) acc[mt][nt][q] = 0.f;

    const uint4* xg = (const uint4*)g_xs16;
    const uint4* wg = (const uint4*)g_WT16;
    const int sr = t >> 2, sq = t & 3;
    constexpr int S = 16;

    uint4 a0, a1, b0, b1;
    auto ldgS = [&](int s) {
        int kq = s * 4;
        a0 = __ldg(&xg[(n0 + sr) * 128 + kq + sq]);
        a1 = __ldg(&xg[(n0 + sr + 64) * 128 + kq + sq]);
        b0 = __ldg(&wg[(head * 128 + sr) * 64 + kq + sq]);
        b1 = __ldg(&wg[(head * 128 + sr + 64) * 64 + kq + sq]);
    };
    auto stsS = [&](int buf) {
        *(uint4*)&GS[buf * 2560 + sr * PST + sq * 4]        = a0;
        *(uint4*)&GS[buf * 2560 + (sr + 64) * PST + sq * 4] = a1;
        *(uint4*)&GS[5120 + buf * 2560 + sr * PST + sq * 4]        = b0;
        *(uint4*)&GS[5120 + buf * 2560 + (sr + 64) * PST + sq * 4] = b1;
    };

    ldgS(0); stsS(0);
    ldgS(1);
    __syncthreads();

    for (int s = 0; s < S; s++) {
        const unsigned mo = (s & 1) ? 10240u : 0u;
#pragma unroll
        for (int ks = 0; ks < 2; ks++) {
            unsigned af0[4], af1[4];
            ldmatrix_x4(af0, aaddr[0][ks] + mo);
            ldmatrix_x4(af1, aaddr[1][ks] + mo);
            unsigned b0a[4], b0b[4], b1a[4], b1b[4];
            ldmatrix_x4(b0a, baddr[ks][0][0] + mo);
            ldmatrix_x4(b0b, baddr[ks][0][1] + mo);
            ldmatrix_x4(b1a, baddr[ks][1][0] + mo);
            ldmatrix_x4(b1b, baddr[ks][1][1] + mo);
#pragma unroll
            for (int nt = 0; nt < 8; nt++) {
                unsigned bb0 = (nt < 4) ? b0a[nt] : b0b[nt - 4];
                unsigned bb1 = (nt < 4) ? b1a[nt] : b1b[nt - 4];
                mma_bf16(acc[0][nt], af0, bb0, bb1);
                mma_bf16(acc[1][nt], af1, bb0, bb1);
            }
        }
        if (s + 1 < S) {
            stsS((s + 1) & 1);
            if (s + 2 < S) ldgS(s + 2);
        }
        __syncthreads();
    }

    float2 wiv[8], wjv[8];
#pragma unroll
    for (int nt = 0; nt < 8; nt++) {
        int c = warp_f + nt * 8 + 2 * tig;
        wiv[nt] = __ldg((const float2*)&wi[head * HEAD_F + c]);
        wjv[nt] = __ldg((const float2*)&wj[head * HEAD_F + c]);
    }
    float pi[2][2] = {{0.f, 0.f}, {0.f, 0.f}};
    float pj[2][2] = {{0.f, 0.f}, {0.f, 0.f}};
#pragma unroll
    for (int mt = 0; mt < 2; mt++)
#pragma unroll
        for (int nt = 0; nt < 8; nt++) {
            pi[mt][0] += acc[mt][nt][0] * wiv[nt].x + acc[mt][nt][1] * wiv[nt].y;
            pi[mt][1] += acc[mt][nt][2] * wiv[nt].x + acc[mt][nt][3] * wiv[nt].y;
            pj[mt][0] += acc[mt][nt][0] * wjv[nt].x + acc[mt][nt][1] * wjv[nt].y;
            pj[mt][1] += acc[mt][nt][2] * wjv[nt].x + acc[mt][nt][3] * wjv[nt].y;
        }
#pragma unroll
    for (int o = 1; o < 4; o <<= 1)
#pragma unroll
        for (int mt = 0; mt < 2; mt++)
#pragma unroll
            for (int h2 = 0; h2 < 2; h2++) {
                pi[mt][h2] += __shfl_xor_sync(0xffffffffu, pi[mt][h2], o);
                pj[mt][h2] += __shfl_xor_sync(0xffffffffu, pj[mt][h2], o);
            }
    if (tig == 0) {
        int wn = w >> 2;
#pragma unroll
        for (int mt = 0; mt < 2; mt++) {
            int rr = warp_m + mt * 16 + g;
            partI[wn][rr]     = pi[mt][0];
            partI[wn][rr + 8] = pi[mt][1];
            partJ[wn][rr]     = pj[mt][0];
            partJ[wn][rr + 8] = pj[mt][1];
        }
    }

    unsigned short* hs = (unsigned short*)GS;
#pragma unroll
    for (int mt = 0; mt < 2; mt++)
#pragma unroll
        for (int nt = 0; nt < 8; nt++) {
            int c = warp_f + nt * 8 + 2 * tig;
            int rl0 = warp_m + mt * 16 + g, rl1 = rl0 + 8;
            hs[c * 136 + rl0]       = bf16b(acc[mt][nt][0]);
            hs[(c + 1) * 136 + rl0] = bf16b(acc[mt][nt][1]);
            hs[c * 136 + rl1]       = bf16b(acc[mt][nt][2]);
            hs[(c + 1) * 136 + rl1] = bf16b(acc[mt][nt][3]);
        }
    __syncthreads();

#pragma unroll
    for (int i = 0; i < 8; i++) {
        int id = i * 256 + t;
        int f = id >> 4, nq = id & 15;
        uint4 v = *(const uint4*)&hs[f * 136 + nq * 8];
        *(uint4*)&g_hT16[(head * 128 + f) * N_NODES + n0 + nq * 8] = v;
    }
    if (t < 128) {
        float ci = partI[0][t] + partI[1][t];
        float cj = partJ[0][t] + partJ[1][t];
        g_ci4[head * N_NODES + n0 + t] = make_float4(ci, __expf(ci), __expf(0.2f * ci), 0.f);
        g_cj4[head * N_NODES + n0 + t] = make_float4(cj, __expf(cj), __expf(0.2f * cj), 0.f);
    }
}

// ---------------------------------------------------------------------------
// Residual GEMM (tensor, K=1536, cp.async staged): g_res = x@W_r + bias
// ---------------------------------------------------------------------------
__global__ __launch_bounds__(256, 2) void res_kernel(const float* __restrict__ bias)
{
    constexpr int PST = 20;
    constexpr unsigned BUFB = 128 * PST * 4u;
    __shared__ unsigned A2[2][128 * PST];
    __shared__ unsigned B2[2][128 * PST];

    const int t = threadIdx.x;
    const int w = t >> 5, lane = t & 31;
    const int g = lane >> 2, tig = lane & 3;
    const int warp_m = (w & 3) * 32;
    const int warp_f = (w >> 2) * 64;
    const int n0 = blockIdx.x * 128, head = blockIdx.y;

    const unsigned Ab = smem_u32(A2[0]), Bb = smem_u32(B2[0]);
    unsigned aaddr[2][2], baddr[2][2][2];
    {
        int arow = warp_m + (lane & 15);
        int ak   = (lane >> 4) << 2;
#pragma unroll
        for (int mt = 0; mt < 2; mt++)
#pragma unroll
            for (int ks = 0; ks < 2; ks++)
                aaddr[mt][ks] = Ab + 4u * ((arow + mt * 16) * PST + ks * 8 + ak);
        int brow = warp_f + (lane >> 3) * 8 + (lane & 7);
#pragma unroll
        for (int ks = 0; ks < 2; ks++)
#pragma unroll
            for (int hf = 0; hf < 2; hf++)
#pragma unroll
                for (int ng = 0; ng < 2; ng++)
                    baddr[ks][hf][ng] = Bb + 4u * ((brow + ng * 32) * PST + ks * 8 + hf * 4);
    }

    float acc[2][8][4];
#pragma unroll
    for (int mt = 0; mt < 2; mt++)
#pragma unroll
        for (int nt = 0; nt < 8; nt++)
#pragma unroll
            for (int q = 0; q < 4; q++) acc[mt][nt][q] = 0.f;

    const int sr = t >> 2, sq = t & 3;
    constexpr int S = 48;
    const char* xb = (const char*)g_xs16;     // row = 2048 B ([hi|lo])
    const char* wb = (const char*)g_WrT16;    // row = 3072 B
    const unsigned dA0 = Ab + 4u * (sr * PST + sq * 4);
    const unsigned dA1 = Ab + 4u * ((sr + 64) * PST + sq * 4);
    const unsigned dB0 = Bb + 4u * (sr * PST + sq * 4);
    const unsigned dB1 = Bb + 4u * ((sr + 64) * PST + sq * 4);

    auto cpa = [&](int s, int buf) {
        int k3 = s * 32;
        int akB = (((k3 < 1024) ? k3 : (k3 - 1024)) + sq * 8) * 2;   // bytes in row
        int bkB = (k3 + sq * 8) * 2;
        unsigned bo = buf ? BUFB : 0u;
        CP_ASYNC16(dA0 + bo, xb + (size_t)(n0 + sr) * 2048 + akB);
        CP_ASYNC16(dA1 + bo, xb + (size_t)(n0 + sr + 64) * 2048 + akB);
        CP_ASYNC16(dB0 + bo, wb + (size_t)(head * 128 + sr) * 3072 + bkB);
        CP_ASYNC16(dB1 + bo, wb + (size_t)(head * 128 + sr + 64) * 3072 + bkB);
        CP_COMMIT();
    };

    cpa(0, 0);
    CP_WAIT0();
    __syncthreads();

    for (int s = 0; s < S; s++) {
        if (s + 1 < S) cpa(s + 1, (s + 1) & 1);
        const unsigned mo = (s & 1) ? BUFB : 0u;
#pragma unroll
        for (int ks = 0; ks < 2; ks++) {
            unsigned af0[4], af1[4];
            ldmatrix_x4(af0, aaddr[0][ks] + mo);
            ldmatrix_x4(af1, aaddr[1][ks] + mo);
            unsigned b0a[4], b0b[4], b1a[4], b1b[4];
            ldmatrix_x4(b0a, baddr[ks][0][0] + mo);
            ldmatrix_x4(b0b, baddr[ks][0][1] + mo);
            ldmatrix_x4(b1a, baddr[ks][1][0] + mo);
            ldmatrix_x4(b1b, baddr[ks][1][1] + mo);
#pragma unroll
            for (int nt = 0; nt < 8; nt++) {
                unsigned bb0 = (nt < 4) ? b0a[nt] : b0b[nt - 4];
                unsigned bb1 = (nt < 4) ? b1a[nt] : b1b[nt - 4];
                mma_bf16(acc[0][nt], af0, bb0, bb1);
                mma_bf16(acc[1][nt], af1, bb0, bb1);
            }
        }
        CP_WAIT0();
        __syncthreads();
    }

#pragma unroll
    for (int mt = 0; mt < 2; mt++) {
        const int rl0 = warp_m + mt * 16 + g;
        const int rl1 = rl0 + 8;
#pragma unroll
        for (int nt = 0; nt < 8; nt++) {
            const int col = head * HEAD_F + warp_f + nt * 8 + 2 * tig;
            float2 bb = *(const float2*)&bias[col];
            *(float2*)&g_res[(n0 + rl0) * OUT_F + col] =
                make_float2(acc[mt][nt][0] + bb.x, acc[mt][nt][1] + bb.y);
            *(float2*)&g_res[(n0 + rl1) * OUT_F + col] =
                make_float2(acc[mt][nt][2] + bb.x, acc[mt][nt][3] + bb.y);
        }
    }
}

// ---------------------------------------------------------------------------
// KEY-SPLIT attention: CTA = (128 rows, head, key-half). 64 key tiles/CTA.
// cp.async Ht staging, double-buffered, 1 sync/tile.
// Writes UNNORMALIZED partial acc to g_att[kh] + partial rsum to g_rsum[kh].
// ---------------------------------------------------------------------------
__global__ __launch_bounds__(256, 2) void attn_kernel()
{
    constexpr int PST = 20;
    constexpr unsigned PBUF = 128 * PST * 4u;
    constexpr int T2 = (N_NODES / 32) / 2;   // 64 tiles per key-half
    __shared__ unsigned P2[2][128 * PST];
    __shared__ unsigned H2[2][128 * PST];
    __shared__ float cjx[2][32], cja[2][32], cjb[2][32];
    __shared__ float sum_s[2][128];

    const int t = threadIdx.x;
    const int w = t >> 5, lane = t & 31;
    const int g = lane >> 2, tig = lane & 3;
    const int warp_m = (w & 3) * 32;
    const int warp_n = (w >> 2) * 64;
    const int n0 = blockIdx.x * 128, head = blockIdx.y, kh = blockIdx.z;
    const int gt0 = kh * T2;                 // first global key tile

    const unsigned Pb = smem_u32(P2[0]), Hb = smem_u32(H2[0]);
    unsigned aaddr[2][2], baddr[2][2][2];
    {
        int arow = warp_m + (lane & 15);
        int ak   = (lane >> 4) << 2;
#pragma unroll
        for (int mt = 0; mt < 2; mt++)
#pragma unroll
            for (int ks = 0; ks < 2; ks++)
                aaddr[mt][ks] = Pb + 4u * ((arow + mt * 16) * PST + ks * 8 + ak);
        int brow = warp_n + (lane >> 3) * 8 + (lane & 7);
#pragma unroll
        for (int ks = 0; ks < 2; ks++)
#pragma unroll
            for (int hf = 0; hf < 2; hf++)
#pragma unroll
                for (int ng = 0; ng < 2; ng++)
                    baddr[ks][hf][ng] = Hb + 4u * ((brow + ng * 32) * PST + ks * 8 + hf * 4);
    }

    const int r = t & 127, half = t >> 7;
    const float4 ci = g_ci4[head * N_NODES + n0 + r];
    float rsum = 0.f;

    float acc[2][8][4];
#pragma unroll
    for (int mt = 0; mt < 2; mt++)
#pragma unroll
        for (int nt = 0; nt < 8; nt++)
#pragma unroll
            for (int q = 0; q < 4; q++) acc[mt][nt][q] = 0.f;

    // cp.async staging addresses (row hTf and hTf+64, 16B each)
    const int hTf = t >> 2, hTq = t & 3;
    const char* hb0 = (const char*)g_hT16 + (size_t)(head * 128 + hTf) * (N_NODES * 2) + hTq * 16;
    const char* hb1 = (const char*)g_hT16 + (size_t)(head * 128 + hTf + 64) * (N_NODES * 2) + hTq * 16;
    const unsigned dH0 = Hb + 4u * (hTf * PST + hTq * 4);
    const unsigned dH1 = Hb + 4u * ((hTf + 64) * PST + hTq * 4);

    auto cpaH = [&](int gt, int buf) {
        unsigned bo = buf ? PBUF : 0u;
        CP_ASYNC16(dH0 + bo, hb0 + (size_t)gt * 64);
        CP_ASYNC16(dH1 + bo, hb1 + (size_t)gt * 64);
        CP_COMMIT();
    };

    auto buildP = [&](int buf, unsigned m) {
        unsigned pw[8];
#pragma unroll
        for (int j2 = 0; j2 < 8; j2++) {
            const int k = half * 16 + j2 * 2;
            float s0 = ci.x + cjx[buf][k];
            float pa0 = s0 > 0.f ? ci.y : ci.z;
            float pb0 = s0 > 0.f ? cja[buf][k] : cjb[buf][k];
            float p0 = ((m >> k) & 1u) ? pa0 * pb0 : 0.f;
            float s1 = ci.x + cjx[buf][k + 1];
            float pa1 = s1 > 0.f ? ci.y : ci.z;
            float pb1 = s1 > 0.f ? cja[buf][k + 1] : cjb[buf][k + 1];
            float p1 = ((m >> (k + 1)) & 1u) ? pa1 * pb1 : 0.f;
            pw[j2] = pack_bf16x2(p0, p1);
            float2 pr = unpack_bf16x2(pw[j2]);
            rsum += pr.x + pr.y;
        }
        *(uint4*)&P2[buf][r * PST + half * 8]     = make_uint4(pw[0], pw[1], pw[2], pw[3]);
        *(uint4*)&P2[buf][r * PST + half * 8 + 4] = make_uint4(pw[4], pw[5], pw[6], pw[7]);
    };

    // ---- prologue ----------------------------------------------------------
    if (t < 32) {
        float4 c4 = __ldg(&g_cj4[head * N_NODES + gt0 * 32 + t]);
        cjx[0][t] = c4.x; cja[0][t] = c4.y; cjb[0][t] = c4.z;
    }
    unsigned mreg = __ldg(&g_maskT[gt0 * N_NODES + n0 + r]);
    __syncthreads();                         // cj(0) visible
    cpaH(gt0, 0);
    buildP(0, mreg);
    if (t < 32) {
        float4 c4 = __ldg(&g_cj4[head * N_NODES + (gt0 + 1) * 32 + t]);
        cjx[1][t] = c4.x; cja[1][t] = c4.y; cjb[1][t] = c4.z;
    }
    mreg = __ldg(&g_maskT[(gt0 + 1) * N_NODES + n0 + r]);
    CP_WAIT0();
    __syncthreads();

    for (int tile = 0; tile < T2; ++tile) {
        const int cur = tile & 1, nb = cur ^ 1;
        const unsigned mo = cur ? PBUF : 0u;
        const bool more = (tile + 1 < T2);
        float4 cjn; unsigned mn = 0;
        if (more) {
            cpaH(gt0 + tile + 1, nb);
            if (t < 32 && tile + 2 < T2)
                cjn = __ldg(&g_cj4[head * N_NODES + (gt0 + tile + 2) * 32 + t]);
            if (tile + 2 < T2)
                mn = __ldg(&g_maskT[(gt0 + tile + 2) * N_NODES + n0 + r]);
            buildP(nb, mreg);
        }

        // ---- mma(tile) ----------------------------------------------------
#pragma unroll
        for (int ks = 0; ks < 2; ks++) {
            unsigned af0[4], af1[4];
            ldmatrix_x4(af0, aaddr[0][ks] + mo);
            ldmatrix_x4(af1, aaddr[1][ks] + mo);
            unsigned b0a[4], b0b[4], b1a[4], b1b[4];
            ldmatrix_x4(b0a, baddr[ks][0][0] + mo);
            ldmatrix_x4(b0b, baddr[ks][0][1] + mo);
            ldmatrix_x4(b1a, baddr[ks][1][0] + mo);
            ldmatrix_x4(b1b, baddr[ks][1][1] + mo);
#pragma unroll
            for (int nt = 0; nt < 8; nt++) {
                unsigned b0 = (nt < 4) ? b0a[nt] : b0b[nt - 4];
                unsigned b1 = (nt < 4) ? b1a[nt] : b1b[nt - 4];
                mma_bf16(acc[0][nt], af0, b0, b1);
                mma_bf16(acc[1][nt], af1, b0, b1);
            }
        }

        if (more) {
            if (t < 32 && tile + 2 < T2) {
                cjx[cur][t] = cjn.x;
                cja[cur][t] = cjn.y;
                cjb[cur][t] = cjn.z;
            }
            mreg = mn;
        }
        CP_WAIT0();
        __syncthreads();
    }

    sum_s[half][r] = rsum;
    __syncthreads();

    // ---- epilogue: UNNORMALIZED partial stores -----------------------------
    float* ap = g_att + (size_t)kh * (N_NODES * OUT_F);
    if (t < 128)
        g_rsum[kh][head * N_NODES + n0 + t] = sum_s[0][t] + sum_s[1][t];
#pragma unroll
    for (int mt = 0; mt < 2; mt++) {
        const int rl0 = warp_m + mt * 16 + g;
        const int rl1 = rl0 + 8;
#pragma unroll
        for (int nt = 0; nt < 8; nt++) {
            const int col = head * HEAD_F + warp_n + nt * 8 + 2 * tig;
            *(float2*)&ap[(n0 + rl0) * OUT_F + col] =
                make_float2(acc[mt][nt][0], acc[mt][nt][1]);
            *(float2*)&ap[(n0 + rl1) * OUT_F + col] =
                make_float2(acc[mt][nt][2], acc[mt][nt][3]);
        }
    }
}

// ---------------------------------------------------------------------------
// combine: out = (att0 + att1) / (rsum0 + rsum1) + res
// ---------------------------------------------------------------------------
__global__ __launch_bounds__(256) void combine_kernel(float* __restrict__ out)
{
    int i = blockIdx.x * 256 + threadIdx.x;       // float4 index
    int n = i >> 8;                               // 256 float4 per row
    int head = (i & 255) >> 5;                    // 32 float4 per head
    float rs = g_rsum[0][head * N_NODES + n] + g_rsum[1][head * N_NODES + n];
    float inv = 1.f / rs;
    float4 a0 = ((const float4*)g_att)[i];
    float4 a1 = ((const float4*)g_att)[i + (N_NODES * OUT_F) / 4];
    float4 rr = ((const float4*)g_res)[i];
    float4 o;
    o.x = (a0.x + a1.x) * inv + rr.x;
    o.y = (a0.y + a1.y) * inv + rr.y;
    o.z = (a0.z + a1.z) * inv + rr.z;
    o.w = (a0.w + a1.w) * inv + rr.w;
    ((float4*)out)[i] = o;
}

// ---------------------------------------------------------------------------
extern "C" void kernel_launch(void* const* d_in, const int* in_sizes, int n_in,
                              void* d_out, int out_size)
{
    const float* x     = (const float*)d_in[0];
    const int*   graph = (const int*)  d_in[1];
    const float* W     = (const float*)d_in[2];
    const float* w_i   = (const float*)d_in[3];
    const float* w_j   = (const float*)d_in[4];
    const float* W_r   = (const float*)d_in[5];
    const float* bias  = (const float*)d_in[6];
    float* out = (float*)d_out;

    // Streams/events created ONCE on first call (before the pre-capture
    // baseline); reused every call — no allocation during capture/replay.
    static cudaStream_t s1 = nullptr, s2 = nullptr;
    static cudaEvent_t e_fork = nullptr, e_x = nullptr, e_res = nullptr, e_m = nullptr;
    if (s1 == nullptr) {
        cudaStreamCreateWithFlags(&s1, cudaStreamNonBlocking);
        cudaStreamCreateWithFlags(&s2, cudaStreamNonBlocking);
        cudaEventCreateWithFlags(&e_fork, cudaEventDisableTiming);
        cudaEventCreateWithFlags(&e_x,    cudaEventDisableTiming);
        cudaEventCreateWithFlags(&e_res,  cudaEventDisableTiming);
        cudaEventCreateWithFlags(&e_m,    cudaEventDisableTiming);
    }

    cudaEventRecord(e_fork, 0);
    cudaStreamWaitEvent(s1, e_fork, 0);
    cudaStreamWaitEvent(s2, e_fork, 0);

    // s2: mask build (DRAM-bound) — overlaps tensor kernels
    maskt_kernel<<<dim3(N_NODES / 32, 4), 256, 0, s2>>>(graph);
    cudaEventRecord(e_m, s2);

    // s0 (null): x split -> wT -> gemm(+coe+hT)
    xsplit_kernel<<<(N_NODES * IN_F / 2) / 256, 256>>>(x);
    cudaEventRecord(e_x, 0);
    wT_kernel<<<dim3(IN_F / 32, HEAD_F / 32, HEADS), 256>>>(W);
    gemm_bf16_kernel<<<dim3(N_NODES / 128, HEADS), 256>>>(w_i, w_j);

    // s1: wrT -> (wait xsplit) -> res (concurrent with gemm + attn)
    wrT_kernel<<<dim3(IN_F / 32, OUT_F / 32), 256, 0, s1>>>(W_r);
    cudaStreamWaitEvent(s1, e_x, 0);
    res_kernel<<<dim3(N_NODES / 128, HEADS), 256, 0, s1>>>(bias);
    cudaEventRecord(e_res, s1);

    // s0: key-split attention (needs gemm in program order + maskt)
    cudaStreamWaitEvent(0, e_m, 0);
    attn_kernel<<<dim3(N_NODES / 128, HEADS, 2), 256>>>();

    // join res, then merge partials + residual
    cudaStreamWaitEvent(0, e_res, 0);
    combine_kernel<<<(N_NODES * OUT_F / 4) / 256, 256>>>(out);
}